// round 12
// baseline (speedup 1.0000x reference)
#include <cuda_runtime.h>
#include <cuda_bf16.h>
#include <math.h>
#include <stdint.h>

// Problem constants
#define B_    4
#define TQ_   1024
#define TKV_  1024
#define D_    1024
#define H_    16
#define HD_   64
#define EPS_  1e-5f

// ===========================================================================
// PTX helpers (baseline features only — compute_103 virtual arch safe)
// ===========================================================================
__device__ __forceinline__ uint32_t smem_to_u32(const void* smem_ptr) {
    uint32_t addr;
    asm("{ .reg .u64 tmp; cvta.to.shared.u64 tmp, %1; cvt.u32.u64 %0, tmp; }"
        : "=r"(addr) : "l"(smem_ptr));
    return addr;
}

__device__ __forceinline__ void cp_async16(uint32_t dst, const void* src) {
    asm volatile("cp.async.cg.shared.global [%0], [%1], 16;" :: "r"(dst), "l"(src));
}
#define CP_COMMIT() asm volatile("cp.async.commit_group;" ::: "memory")
#define CP_WAIT(n)  asm volatile("cp.async.wait_group %0;" :: "n"(n) : "memory")

__device__ __forceinline__ void ldsm_x4(uint32_t& r0, uint32_t& r1, uint32_t& r2,
                                        uint32_t& r3, uint32_t addr) {
    asm volatile("ldmatrix.sync.aligned.m8n8.x4.shared.b16 {%0,%1,%2,%3}, [%4];"
        : "=r"(r0), "=r"(r1), "=r"(r2), "=r"(r3) : "r"(addr));
}

__device__ __forceinline__ void ldsm_x4_t(uint32_t& r0, uint32_t& r1, uint32_t& r2,
                                          uint32_t& r3, uint32_t addr) {
    asm volatile("ldmatrix.sync.aligned.m8n8.x4.trans.shared.b16 {%0,%1,%2,%3}, [%4];"
        : "=r"(r0), "=r"(r1), "=r"(r2), "=r"(r3) : "r"(addr));
}

// D += A * B  (m16n8k16, bf16 inputs, fp32 accum)
__device__ __forceinline__ void mma16816(float* d, const uint32_t* a,
                                         uint32_t b0, uint32_t b1) {
    asm volatile(
        "mma.sync.aligned.m16n8k16.row.col.f32.bf16.bf16.f32 "
        "{%0,%1,%2,%3}, {%4,%5,%6,%7}, {%8,%9}, {%0,%1,%2,%3};"
        : "+f"(d[0]), "+f"(d[1]), "+f"(d[2]), "+f"(d[3])
        : "r"(a[0]), "r"(a[1]), "r"(a[2]), "r"(a[3]), "r"(b0), "r"(b1));
}

__device__ __forceinline__ uint32_t pack_bf16(float a, float b) {
    __nv_bfloat162 t = __floats2bfloat162_rn(a, b);
    return *reinterpret_cast<uint32_t*>(&t);
}

__device__ __forceinline__ float lds_f32(uint32_t addr) {
    float f;
    asm volatile("ld.shared.f32 %0, [%1];" : "=f"(f) : "r"(addr));
    return f;
}
__device__ __forceinline__ void sts_b32(uint32_t addr, uint32_t v) {
    asm volatile("st.shared.b32 [%0], %1;" :: "r"(addr), "r"(v));
}

// ===========================================================================
// Device scratch
// ===========================================================================
__device__ float g_y     [B_ * H_ * TQ_  * HD_];

__device__ __nv_bfloat16 g_xq_hi [B_ * TQ_ * D_];
__device__ __nv_bfloat16 g_xq_lo [B_ * TQ_ * D_];
__device__ __nv_bfloat16 g_xkv_hi[B_ * TKV_ * D_];
__device__ __nv_bfloat16 g_xkv_lo[B_ * TKV_ * D_];
__device__ __nv_bfloat16 g_ybt_hi [B_ * TQ_ * D_];
__device__ __nv_bfloat16 g_ybt_lo [B_ * TQ_ * D_];

// bf16 hi/lo attention operands, (B,H,T,HD)
__device__ __nv_bfloat16 g_q1h[B_ * H_ * TQ_ * HD_];
__device__ __nv_bfloat16 g_q1l[B_ * H_ * TQ_ * HD_];
__device__ __nv_bfloat16 g_q2h[B_ * H_ * TQ_ * HD_];
__device__ __nv_bfloat16 g_q2l[B_ * H_ * TQ_ * HD_];
__device__ __nv_bfloat16 g_k1h[B_ * H_ * TKV_ * HD_];
__device__ __nv_bfloat16 g_k1l[B_ * H_ * TKV_ * HD_];
__device__ __nv_bfloat16 g_k2h[B_ * H_ * TKV_ * HD_];
__device__ __nv_bfloat16 g_k2l[B_ * H_ * TKV_ * HD_];
__device__ __nv_bfloat16 g_vhh[B_ * H_ * TKV_ * HD_];
__device__ __nv_bfloat16 g_vhl[B_ * H_ * TKV_ * HD_];

// ===========================================================================
// Split fp32 -> bf16 hi/lo (both x tensors in one launch; grid.y selects)
// ===========================================================================
__global__ void split2_kernel(const float* __restrict__ xa,
                              __nv_bfloat16* __restrict__ hia, __nv_bfloat16* __restrict__ loa,
                              const float* __restrict__ xb,
                              __nv_bfloat16* __restrict__ hib, __nv_bfloat16* __restrict__ lob,
                              int n4)
{
    const int i = blockIdx.x * blockDim.x + threadIdx.x;
    if (i >= n4) return;
    const float* x = blockIdx.y ? xb : xa;
    __nv_bfloat16* hi = blockIdx.y ? hib : hia;
    __nv_bfloat16* lo = blockIdx.y ? lob : loa;
    float4 v = ((const float4*)x)[i];
    float f[4] = {v.x, v.y, v.z, v.w};
    __nv_bfloat16 h[4], l[4];
    #pragma unroll
    for (int j = 0; j < 4; j++) {
        h[j] = __float2bfloat16_rn(f[j]);
        l[j] = __float2bfloat16_rn(f[j] - __bfloat162float(h[j]));
    }
    ((__nv_bfloat162*)hi)[2*i + 0] = __nv_bfloat162(h[0], h[1]);
    ((__nv_bfloat162*)hi)[2*i + 1] = __nv_bfloat162(h[2], h[3]);
    ((__nv_bfloat162*)lo)[2*i + 0] = __nv_bfloat162(l[0], l[1]);
    ((__nv_bfloat162*)lo)[2*i + 1] = __nv_bfloat162(l[2], l[3]);
}

// ===========================================================================
// GEMM with fused on-the-fly W transpose+split.
//   A: bf16 hi/lo [M,K] row-major (pre-split)
//   W: fp32 [K,N] row-major (raw!)  -> converted in-loop to Bt [N,K] bf16 hi/lo
// CTA tile 128x128, k-chunk 32, 8 warps (warp 64x32).
// smem layout (bytes, GT=10240 = 128 rows * 80B):
//   [0,2GT)       opA buf0 (hi, lo)
//   [2GT,4GT)     opA buf1
//   [4GT,6GT)     opB buf0 (hi, lo)
//   [6GT,8GT)     opB buf1
//   [8GT, +16K)   stgB buf0 (raw fp32 32x128, 512B rows)
//   [+16K, +32K)  stgB buf1
// ===========================================================================
#define GT 10240
#define STG_OFF (8 * GT)          // 81920
#define GM_SMEM (STG_OFF + 2 * 16384)   // 114688 -> 2 CTAs/SM

__device__ __forceinline__ void gm_load_A(
    uint32_t sb, int buf, const __nv_bfloat16* Ahi, const __nv_bfloat16* Alo,
    int k0, int K, int tid)
{
    #pragma unroll
    for (int t2 = 0; t2 < 2; t2++) {
        const __nv_bfloat16* s = (t2 ? Alo : Ahi) + k0;
        const uint32_t tb = sb + buf * 2 * GT + t2 * GT;
        #pragma unroll
        for (int i = 0; i < 2; i++) {
            const int idx = tid + i * 256;
            const int row = idx >> 2, c16 = idx & 3;
            cp_async16(tb + row * 80 + c16 * 16, s + (size_t)row * K + c16 * 8);
        }
    }
}

__device__ __forceinline__ void gm_load_Braw(
    uint32_t sb, int buf, const float* W, int n0, int k0, int N, int tid)
{
    const uint32_t base = sb + STG_OFF + buf * 16384;
    #pragma unroll
    for (int i = 0; i < 4; i++) {
        const int idx = tid + i * 256;           // 1024 chunks of 16B
        const int row = idx >> 5, c16 = idx & 31;  // 32 rows x 32 chunks (512B/row)
        cp_async16(base + row * 512 + c16 * 16,
                   W + (size_t)(k0 + row) * N + n0 + c16 * 4);
    }
}

__device__ __forceinline__ void gm_convert_B(uint32_t sb, int buf, int tid)
{
    const uint32_t stg = sb + STG_OFF + buf * 16384;
    const uint32_t dh  = sb + 4 * GT + buf * 2 * GT;
    const int n = tid >> 1;
    const int ks = (tid & 1) * 16;
    #pragma unroll
    for (int i = 0; i < 8; i++) {
        const int k = ks + 2 * i;
        const float f0 = lds_f32(stg + k * 512 + n * 4);
        const float f1 = lds_f32(stg + (k + 1) * 512 + n * 4);
        const __nv_bfloat16 h0 = __float2bfloat16_rn(f0);
        const __nv_bfloat16 h1 = __float2bfloat16_rn(f1);
        sts_b32(dh + n * 80 + k * 2, pack_bf16(f0, f1));
        sts_b32(dh + GT + n * 80 + k * 2,
                pack_bf16(f0 - __bfloat162float(h0), f1 - __bfloat162float(h1)));
    }
}

// mainloop: fills acc[4][4][4]
__device__ __forceinline__ void gm_mainloop_fw(
    uint32_t sb, const __nv_bfloat16* Ahi, const __nv_bfloat16* Alo,
    const float* W, int n0, int N, int K,
    int tid, int lane, int wm, int wn, float acc[4][4][4])
{
    const int nch = K >> 5;   // 32

    // prologue: group P = {Braw(0)}, group G_{-1} = {A(0), Braw(1)}
    gm_load_Braw(sb, 0, W, n0, 0, N, tid);
    CP_COMMIT();
    gm_load_A(sb, 0, Ahi, Alo, 0, K, tid);
    gm_load_Braw(sb, 1, W, n0, 32, N, tid);
    CP_COMMIT();
    CP_WAIT(1);                 // Braw(0) arrived
    __syncthreads();
    gm_convert_B(sb, 0, tid);   // opB[0] ready
    __syncthreads();

    const uint32_t lrow = (lane & 15);
    const uint32_t lcol16 = (lane >> 4) * 16;

    for (int c = 0; c < nch; c++) {
        const int cur = c & 1, nxt = cur ^ 1;
        // issue G_c = {A(c+1), Braw(c+2)}
        if (c + 1 < nch) gm_load_A(sb, nxt, Ahi, Alo, (c + 1) << 5, K, tid);
        if (c + 2 < nch) gm_load_Braw(sb, cur, W, n0, (c + 2) << 5, N, tid);
        CP_COMMIT();
        CP_WAIT(1);             // G_{c-1} = {A(c), Braw(c+1)} arrived
        __syncthreads();

        // convert Braw(c+1) -> opB[nxt]  (interleaves with MMA below)
        if (c + 1 < nch) gm_convert_B(sb, nxt, tid);

        // MMA on operands[cur]
        const uint32_t stA = sb + cur * 2 * GT;
        const uint32_t stB = sb + 4 * GT + cur * 2 * GT;
        #pragma unroll
        for (int ks = 0; ks < 2; ks++) {
            const uint32_t coff = lcol16 + ks * 32;
            uint32_t bh[2][4], bl[2][4];
            #pragma unroll
            for (int nt = 0; nt < 2; nt++) {
                const uint32_t baddr = stB + (wn * 32 + nt * 16 + lrow) * 80 + coff;
                ldsm_x4(bh[nt][0], bh[nt][1], bh[nt][2], bh[nt][3], baddr);
                ldsm_x4(bl[nt][0], bl[nt][1], bl[nt][2], bl[nt][3], baddr + GT);
            }
            #pragma unroll
            for (int mt = 0; mt < 4; mt++) {
                const uint32_t aaddr = stA + (wm * 64 + mt * 16 + lrow) * 80 + coff;
                uint32_t ah[4], al[4];
                ldsm_x4(ah[0], ah[1], ah[2], ah[3], aaddr);
                ldsm_x4(al[0], al[1], al[2], al[3], aaddr + GT);
                #pragma unroll
                for (int nt = 0; nt < 2; nt++) {
                    #pragma unroll
                    for (int hh = 0; hh < 2; hh++) {
                        float* d = acc[mt][nt * 2 + hh];
                        uint32_t bfh0 = bh[nt][hh], bfh1 = bh[nt][hh + 2];
                        mma16816(d, ah, bfh0, bfh1);
                        mma16816(d, ah, bl[nt][hh], bl[nt][hh + 2]);
                        mma16816(d, al, bfh0, bfh1);
                    }
                }
            }
        }
        __syncthreads();
    }
}

// ---- plain epilogue variant (fp32 C) — out-projection ----
__global__ __launch_bounds__(256, 2) void gemm_fw(
    const __nv_bfloat16* __restrict__ Ahi, const __nv_bfloat16* __restrict__ Alo,
    const float* __restrict__ W, float* __restrict__ C, int M, int N, int K)
{
    extern __shared__ __align__(128) char smem[];
    const uint32_t sb = smem_to_u32(smem);
    const int tid = threadIdx.x;
    const int lane = tid & 31;
    const int wid = tid >> 5;
    const int wm = wid & 1, wn = wid >> 1;
    const int bx = blockIdx.x, by = blockIdx.y;

    float acc[4][4][4];
    #pragma unroll
    for (int a = 0; a < 4; a++)
        #pragma unroll
        for (int b = 0; b < 4; b++)
            #pragma unroll
            for (int c = 0; c < 4; c++) acc[a][b][c] = 0.f;

    gm_mainloop_fw(sb, Ahi + (size_t)(by * 128) * K, Alo + (size_t)(by * 128) * K,
                   W, bx * 128, N, K, tid, lane, wm, wn, acc);

    #pragma unroll
    for (int mt = 0; mt < 4; mt++) {
        const int row0 = by * 128 + wm * 64 + mt * 16 + (lane >> 2);
        #pragma unroll
        for (int n8 = 0; n8 < 4; n8++) {
            const int col = bx * 128 + wn * 32 + n8 * 8 + (lane & 3) * 2;
            *(float2*)&C[(size_t)row0 * N + col]       = make_float2(acc[mt][n8][0], acc[mt][n8][1]);
            *(float2*)&C[(size_t)(row0 + 8) * N + col] = make_float2(acc[mt][n8][2], acc[mt][n8][3]);
        }
    }
}

// ---- RMS epilogue variant: fused RMSNorm + head-reshape + bf16 split ----
struct RmsDst {
    const float* w0;
    const float* w1;
    __nv_bfloat16 *h0, *l0;
    __nv_bfloat16 *h1, *l1;
    __nv_bfloat16 *h2, *l2;
    float qscale;
};

__global__ __launch_bounds__(256, 2) void gemm_fw_rms(
    const __nv_bfloat16* __restrict__ Ahi, const __nv_bfloat16* __restrict__ Alo,
    const float* __restrict__ W, RmsDst P, int M, int N, int K)
{
    extern __shared__ __align__(128) char smem[];
    const uint32_t sb = smem_to_u32(smem);
    const int tid = threadIdx.x;
    const int lane = tid & 31;
    const int wid = tid >> 5;
    const int wm = wid & 1, wn = wid >> 1;
    const int bx = blockIdx.x, by = blockIdx.y;

    float acc[4][4][4];
    #pragma unroll
    for (int a = 0; a < 4; a++)
        #pragma unroll
        for (int b = 0; b < 4; b++)
            #pragma unroll
            for (int c = 0; c < 4; c++) acc[a][b][c] = 0.f;

    gm_mainloop_fw(sb, Ahi + (size_t)(by * 128) * K, Alo + (size_t)(by * 128) * K,
                   W, bx * 128, N, K, tid, lane, wm, wn, acc);

    // acc -> smem fp32 tile [128][132]
    float* sE = (float*)smem;
    #pragma unroll
    for (int mt = 0; mt < 4; mt++) {
        const int r0 = wm * 64 + mt * 16 + (lane >> 2);
        #pragma unroll
        for (int n8 = 0; n8 < 4; n8++) {
            const int c = wn * 32 + n8 * 8 + (lane & 3) * 2;
            *(float2*)&sE[r0 * 132 + c]       = make_float2(acc[mt][n8][0], acc[mt][n8][1]);
            *(float2*)&sE[(r0 + 8) * 132 + c] = make_float2(acc[mt][n8][2], acc[mt][n8][3]);
        }
    }
    __syncthreads();

    const int bq    = by >> 3;
    const int hloc  = lane >> 4;
    const int cg    = bx * 128 + hloc * 64;
    const int which = cg >> 10;
    const int hh    = (cg >> 6) & 15;
    const int d0    = (lane & 15) * 4;
    const bool donorm = (which < 2);
    const float* wptr = (which == 0) ? P.w0 : P.w1;
    float4 wv = make_float4(1.f, 1.f, 1.f, 1.f);
    if (donorm) wv = *(const float4*)&wptr[d0];
    __nv_bfloat16* dh = (which == 0) ? P.h0 : ((which == 1) ? P.h1 : P.h2);
    __nv_bfloat16* dl = (which == 0) ? P.l0 : ((which == 1) ? P.l1 : P.l2);
    const int w8 = wid * 16;

    #pragma unroll 4
    for (int i = 0; i < 16; i++) {
        const int r = w8 + i;
        float4 v = *(const float4*)&sE[r * 132 + lane * 4];
        float ss = v.x * v.x + v.y * v.y + v.z * v.z + v.w * v.w;
        ss += __shfl_xor_sync(0xffffffffu, ss, 1);
        ss += __shfl_xor_sync(0xffffffffu, ss, 2);
        ss += __shfl_xor_sync(0xffffffffu, ss, 4);
        ss += __shfl_xor_sync(0xffffffffu, ss, 8);
        const float rr = donorm ? rsqrtf(ss * (1.0f / 64.0f) + EPS_) * P.qscale : 1.f;
        const float f0 = v.x * rr * wv.x;
        const float f1 = v.y * rr * wv.y;
        const float f2 = v.z * rr * wv.z;
        const float f3 = v.w * rr * wv.w;
        const __nv_bfloat16 b0 = __float2bfloat16_rn(f0);
        const __nv_bfloat16 b1 = __float2bfloat16_rn(f1);
        const __nv_bfloat16 b2 = __float2bfloat16_rn(f2);
        const __nv_bfloat16 b3 = __float2bfloat16_rn(f3);
        const uint32_t H01 = pack_bf16(f0, f1);
        const uint32_t H23 = pack_bf16(f2, f3);
        const uint32_t L01 = pack_bf16(f0 - __bfloat162float(b0), f1 - __bfloat162float(b1));
        const uint32_t L23 = pack_bf16(f2 - __bfloat162float(b2), f3 - __bfloat162float(b3));
        const int t = (by & 7) * 128 + r;
        const size_t idx = ((((size_t)bq * 16 + hh) * 1024) + t) * 64 + d0;
        *(uint2*)&dh[idx] = make_uint2(H01, H23);
        *(uint2*)&dl[idx] = make_uint2(L01, L23);
    }
}

// ===========================================================================
// MERGED dual flash attention with mma.sync bf16x3 (unchanged — passing)
// ===========================================================================
#define FSTR_B    144
#define FQ_TILE   (128 * FSTR_B)
#define FKV_TILE  (64 * FSTR_B)
#define FKV_STAGE (6 * FKV_TILE)
#define FLASH_SMEM (4 * FQ_TILE + 2 * FKV_STAGE)   // 184320

__device__ __forceinline__ void flash_load_kv6(
    uint32_t dst, const __nv_bfloat16* const* srcs, int kt, int tid)
{
    #pragma unroll
    for (int i = 0; i < 12; i++) {
        const int idx = tid + i * 256;
        const int t = idx >> 9;
        const int rem = idx & 511;
        const int row = rem >> 3, c = rem & 7;
        cp_async16(dst + t * FKV_TILE + row * FSTR_B + c * 16,
                   srcs[t] + ((size_t)(kt * 64 + row)) * HD_ + c * 8);
    }
}

__device__ __forceinline__ void softmax_step(float s[8][4], float m[2], float l[2],
                                             float o[8][4])
{
    float mx0 = -1e30f, mx1 = -1e30f;
    #pragma unroll
    for (int j = 0; j < 8; j++) {
        mx0 = fmaxf(mx0, fmaxf(s[j][0], s[j][1]));
        mx1 = fmaxf(mx1, fmaxf(s[j][2], s[j][3]));
    }
    mx0 = fmaxf(mx0, __shfl_xor_sync(0xffffffffu, mx0, 1));
    mx0 = fmaxf(mx0, __shfl_xor_sync(0xffffffffu, mx0, 2));
    mx1 = fmaxf(mx1, __shfl_xor_sync(0xffffffffu, mx1, 1));
    mx1 = fmaxf(mx1, __shfl_xor_sync(0xffffffffu, mx1, 2));
    const float mn0 = fmaxf(m[0], mx0), mn1 = fmaxf(m[1], mx1);
    const float a0 = __expf(m[0] - mn0), a1 = __expf(m[1] - mn1);
    m[0] = mn0; m[1] = mn1;
    float ps0 = 0.f, ps1 = 0.f;
    #pragma unroll
    for (int j = 0; j < 8; j++) {
        s[j][0] = __expf(s[j][0] - mn0);
        s[j][1] = __expf(s[j][1] - mn0);
        s[j][2] = __expf(s[j][2] - mn1);
        s[j][3] = __expf(s[j][3] - mn1);
        ps0 += s[j][0] + s[j][1];
        ps1 += s[j][2] + s[j][3];
    }
    ps0 += __shfl_xor_sync(0xffffffffu, ps0, 1);
    ps0 += __shfl_xor_sync(0xffffffffu, ps0, 2);
    ps1 += __shfl_xor_sync(0xffffffffu, ps1, 1);
    ps1 += __shfl_xor_sync(0xffffffffu, ps1, 2);
    l[0] = l[0] * a0 + ps0;
    l[1] = l[1] * a1 + ps1;
    #pragma unroll
    for (int j = 0; j < 8; j++) {
        o[j][0] *= a0; o[j][1] *= a0;
        o[j][2] *= a1; o[j][3] *= a1;
    }
}

__device__ __forceinline__ void build_p(const float s[8][4],
                                        uint32_t ph[4][4], uint32_t pl[4][4])
{
    #pragma unroll
    for (int kc = 0; kc < 4; kc++) {
        const int j0 = 2 * kc, j1 = 2 * kc + 1;
        ph[kc][0] = pack_bf16(s[j0][0], s[j0][1]);
        ph[kc][1] = pack_bf16(s[j0][2], s[j0][3]);
        ph[kc][2] = pack_bf16(s[j1][0], s[j1][1]);
        ph[kc][3] = pack_bf16(s[j1][2], s[j1][3]);
        float r00 = s[j0][0] - __bfloat162float(__float2bfloat16_rn(s[j0][0]));
        float r01 = s[j0][1] - __bfloat162float(__float2bfloat16_rn(s[j0][1]));
        float r02 = s[j0][2] - __bfloat162float(__float2bfloat16_rn(s[j0][2]));
        float r03 = s[j0][3] - __bfloat162float(__float2bfloat16_rn(s[j0][3]));
        float r10 = s[j1][0] - __bfloat162float(__float2bfloat16_rn(s[j1][0]));
        float r11 = s[j1][1] - __bfloat162float(__float2bfloat16_rn(s[j1][1]));
        float r12 = s[j1][2] - __bfloat162float(__float2bfloat16_rn(s[j1][2]));
        float r13 = s[j1][3] - __bfloat162float(__float2bfloat16_rn(s[j1][3]));
        pl[kc][0] = pack_bf16(r00, r01);
        pl[kc][1] = pack_bf16(r02, r03);
        pl[kc][2] = pack_bf16(r10, r11);
        pl[kc][3] = pack_bf16(r12, r13);
    }
}

__device__ __forceinline__ void pv_step(float o[8][4], const uint32_t ph[4][4],
                                        const uint32_t pl[4][4], uint32_t st,
                                        uint32_t lrow16)
{
    #pragma unroll
    for (int kc = 0; kc < 4; kc++) {
        #pragma unroll
        for (int hg = 0; hg < 4; hg++) {
            const uint32_t addr = st + kc * 16 * FSTR_B + lrow16 + hg * 32;
            uint32_t vh0, vh1, vh2, vh3, vl0, vl1, vl2, vl3;
            ldsm_x4_t(vh0, vh1, vh2, vh3, addr + 4 * FKV_TILE);
            ldsm_x4_t(vl0, vl1, vl2, vl3, addr + 5 * FKV_TILE);
            mma16816(o[2 * hg],     ph[kc], vh0, vh1);
            mma16816(o[2 * hg],     pl[kc], vh0, vh1);
            mma16816(o[2 * hg],     ph[kc], vl0, vl1);
            mma16816(o[2 * hg + 1], ph[kc], vh2, vh3);
            mma16816(o[2 * hg + 1], pl[kc], vh2, vh3);
            mma16816(o[2 * hg + 1], ph[kc], vl2, vl3);
        }
    }
}

__global__ __launch_bounds__(256, 1) void flash_mma_kernel(
    const __nv_bfloat16* __restrict__ q1h, const __nv_bfloat16* __restrict__ q1l,
    const __nv_bfloat16* __restrict__ q2h, const __nv_bfloat16* __restrict__ q2l,
    const __nv_bfloat16* __restrict__ k1h, const __nv_bfloat16* __restrict__ k1l,
    const __nv_bfloat16* __restrict__ k2h, const __nv_bfloat16* __restrict__ k2l,
    const __nv_bfloat16* __restrict__ vhh, const __nv_bfloat16* __restrict__ vhl,
    const float* __restrict__ lmb, float* __restrict__ y)
{
    extern __shared__ __align__(128) char smem[];
    const uint32_t sb = smem_to_u32(smem);
    const uint32_t sQ = sb, sKV = sb + 4 * FQ_TILE;
    const int tid = threadIdx.x;
    const int lane = tid & 31;
    const int w = tid >> 5;
    const int qt = blockIdx.x, h = blockIdx.y, b = blockIdx.z;
    const int bh = b * H_ + h;
    const size_t off = (size_t)bh * TQ_ * HD_;

    const __nv_bfloat16* kvsrc[6] = {
        k1h + off, k1l + off, k2h + off, k2l + off, vhh + off, vhl + off };
    const __nv_bfloat16* qsrc[4] = {
        q1h + off, q1l + off, q2h + off, q2l + off };

    #pragma unroll
    for (int i = 0; i < 16; i++) {
        const int idx = tid + i * 256;
        const int ts = idx >> 10;
        const int rem = idx & 1023;
        const int row = rem >> 3, c = rem & 7;
        cp_async16(sQ + ts * FQ_TILE + row * FSTR_B + c * 16,
                   qsrc[ts] + ((size_t)(qt * 128 + row)) * HD_ + c * 8);
    }
    flash_load_kv6(sKV, kvsrc, 0, tid);
    CP_COMMIT();
    flash_load_kv6(sKV + FKV_STAGE, kvsrc, 1, tid);
    CP_COMMIT();

    float o1[8][4], o2[8][4];
    float m1[2] = {-1e30f, -1e30f}, l1[2] = {0.f, 0.f};
    float m2[2] = {-1e30f, -1e30f}, l2[2] = {0.f, 0.f};
    #pragma unroll
    for (int j = 0; j < 8; j++)
        #pragma unroll
        for (int q = 0; q < 4; q++) { o1[j][q] = 0.f; o2[j][q] = 0.f; }

    CP_WAIT(1);
    __syncthreads();

    const uint32_t qrow = (w * 16 + (lane & 15)) * FSTR_B + (lane >> 4) * 16;
    const uint32_t lrow16 = (lane & 15) * FSTR_B + (lane >> 4) * 16;

    uint32_t q1hf[4][4], q1lf[4][4];
    #pragma unroll
    for (int kc = 0; kc < 4; kc++) {
        ldsm_x4(q1hf[kc][0], q1hf[kc][1], q1hf[kc][2], q1hf[kc][3],
                sQ + qrow + kc * 32);
        ldsm_x4(q1lf[kc][0], q1lf[kc][1], q1lf[kc][2], q1lf[kc][3],
                sQ + FQ_TILE + qrow + kc * 32);
    }

    for (int t = 0; t < 16; t++) {
        if (t > 0) {
            if (t + 1 < 16) { CP_WAIT(1); } else { CP_WAIT(0); }
            __syncthreads();
        }
        const uint32_t st = sKV + (t & 1) * FKV_STAGE;

        // ======== attention 1 ========
        {
            float s[8][4];
            #pragma unroll
            for (int j = 0; j < 8; j++)
                #pragma unroll
                for (int q = 0; q < 4; q++) s[j][q] = 0.f;

            #pragma unroll
            for (int kc = 0; kc < 4; kc++) {
                #pragma unroll
                for (int g = 0; g < 4; g++) {
                    const uint32_t addr = st + g * 16 * FSTR_B + lrow16 + kc * 32;
                    uint32_t h0, h1, h2, h3, l0, l1r, l2r, l3;
                    ldsm_x4(h0, h1, h2, h3, addr);
                    ldsm_x4(l0, l1r, l2r, l3, addr + FKV_TILE);
                    mma16816(s[2 * g],     q1hf[kc], h0, h2);
                    mma16816(s[2 * g],     q1hf[kc], l0, l2r);
                    mma16816(s[2 * g],     q1lf[kc], h0, h2);
                    mma16816(s[2 * g + 1], q1hf[kc], h1, h3);
                    mma16816(s[2 * g + 1], q1hf[kc], l1r, l3);
                    mma16816(s[2 * g + 1], q1lf[kc], h1, h3);
                }
            }
            softmax_step(s, m1, l1, o1);
            uint32_t ph[4][4], pl[4][4];
            build_p(s, ph, pl);
            pv_step(o1, ph, pl, st, lrow16);
        }

        // ======== attention 2 (Q2 frags re-ldsm'd) ========
        {
            float s[8][4];
            #pragma unroll
            for (int j = 0; j < 8; j++)
                #pragma unroll
                for (int q = 0; q < 4; q++) s[j][q] = 0.f;

            #pragma unroll
            for (int kc = 0; kc < 4; kc++) {
                uint32_t qh[4], ql[4];
                ldsm_x4(qh[0], qh[1], qh[2], qh[3], sQ + 2 * FQ_TILE + qrow + kc * 32);
                ldsm_x4(ql[0], ql[1], ql[2], ql[3], sQ + 3 * FQ_TILE + qrow + kc * 32);
                #pragma unroll
                for (int g = 0; g < 4; g++) {
                    const uint32_t addr = st + 2 * FKV_TILE + g * 16 * FSTR_B + lrow16 + kc * 32;
                    uint32_t h0, h1, h2, h3, l0, l1r, l2r, l3;
                    ldsm_x4(h0, h1, h2, h3, addr);
                    ldsm_x4(l0, l1r, l2r, l3, addr + FKV_TILE);
                    mma16816(s[2 * g],     qh, h0, h2);
                    mma16816(s[2 * g],     qh, l0, l2r);
                    mma16816(s[2 * g],     ql, h0, h2);
                    mma16816(s[2 * g + 1], qh, h1, h3);
                    mma16816(s[2 * g + 1], qh, l1r, l3);
                    mma16816(s[2 * g + 1], ql, h1, h3);
                }
            }
            softmax_step(s, m2, l2, o2);
            uint32_t ph[4][4], pl[4][4];
            build_p(s, ph, pl);
            pv_step(o2, ph, pl, st, lrow16);
        }

        __syncthreads();
        if (t + 2 < 16) {
            flash_load_kv6(st, kvsrc, t + 2, tid);
            CP_COMMIT();
        }
    }

    // epilogue
    const float cmul = log1pf(__expf(lmb[h]));
    const int r0 = lane >> 2, cb = (lane & 3) * 2;
    const float il10 = 1.f / l1[0], il11 = 1.f / l1[1];
    const float il20 = cmul / l2[0], il21 = cmul / l2[1];
    const size_t ybase = off + (size_t)(qt * 128 + w * 16) * HD_;
    #pragma unroll
    for (int j = 0; j < 8; j++) {
        float2 v0 = make_float2(o1[j][0] * il10 - o2[j][0] * il20,
                                o1[j][1] * il10 - o2[j][1] * il20);
        float2 v1 = make_float2(o1[j][2] * il11 - o2[j][2] * il21,
                                o1[j][3] * il11 - o2[j][3] * il21);
        *(float2*)&y[ybase + (size_t)r0 * HD_ + j * 8 + cb]       = v0;
        *(float2*)&y[ybase + (size_t)(r0 + 8) * HD_ + j * 8 + cb] = v1;
    }
}

// ===========================================================================
// Merged GroupNorm: stats + apply + transpose + bf16 split, one block per (b,h)
// ===========================================================================
__global__ void gn_fused_kernel(const float* __restrict__ y,
                                const float* __restrict__ gw, const float* __restrict__ gb,
                                __nv_bfloat16* __restrict__ hi, __nv_bfloat16* __restrict__ lo)
{
    __shared__ float rs[256], rq[256];
    __shared__ float s_mu, s_rstd;
    const int bh = blockIdx.x, tid = threadIdx.x;
    const int b = bh >> 4, h = bh & 15;
    const float* p = y + (size_t)bh * TQ_ * HD_;

    float s = 0.f, q = 0.f;
    for (int i = tid * 4; i < TQ_ * HD_; i += 256 * 4) {
        float4 v = *(const float4*)(p + i);
        s += v.x + v.y + v.z + v.w;
        q += v.x * v.x + v.y * v.y + v.z * v.z + v.w * v.w;
    }
    rs[tid] = s; rq[tid] = q;
    __syncthreads();
    for (int o = 128; o; o >>= 1) {
        if (tid < o) { rs[tid] += rs[tid + o]; rq[tid] += rq[tid + o]; }
        __syncthreads();
    }
    if (tid == 0) {
        const float inv = 1.f / (float)(TQ_ * HD_);
        const float mu = rs[0] * inv;
        const float var = rq[0] * inv - mu * mu;
        s_mu = mu;
        s_rstd = rsqrtf(var + EPS_);
    }
    __syncthreads();
    const float mu = s_mu, rstd = s_rstd;

    // apply + transpose: y(bh, t, dd) -> ybt(b, t, h*64+dd)
    for (int i = tid; i < TQ_ * HD_ / 4; i += 256) {
        const int t  = i >> 4;
        const int dd = (i & 15) * 4;
        float4 v = *(const float4*)(p + (size_t)t * HD_ + dd);
        float4 w = *(const float4*)&gw[h * 64 + dd];
        float4 bb = *(const float4*)&gb[h * 64 + dd];
        float f0 = (v.x - mu) * rstd * w.x + bb.x;
        float f1 = (v.y - mu) * rstd * w.y + bb.y;
        float f2 = (v.z - mu) * rstd * w.z + bb.z;
        float f3 = (v.w - mu) * rstd * w.w + bb.w;
        const __nv_bfloat16 b0 = __float2bfloat16_rn(f0);
        const __nv_bfloat16 b1 = __float2bfloat16_rn(f1);
        const __nv_bfloat16 b2 = __float2bfloat16_rn(f2);
        const __nv_bfloat16 b3 = __float2bfloat16_rn(f3);
        const size_t idx = ((size_t)(b * 1024 + t)) * 1024 + h * 64 + dd;
        *(uint2*)&hi[idx] = make_uint2(pack_bf16(f0, f1), pack_bf16(f2, f3));
        *(uint2*)&lo[idx] = make_uint2(
            pack_bf16(f0 - __bfloat162float(b0), f1 - __bfloat162float(b1)),
            pack_bf16(f2 - __bfloat162float(b2), f3 - __bfloat162float(b3)));
    }
}

// ===========================================================================
// Launch
// ===========================================================================
extern "C" void kernel_launch(void* const* d_in, const int* in_sizes, int n_in,
                              void* d_out, int out_size)
{
    const float* x_q  = (const float*)d_in[0];
    const float* x_kv = (const float*)d_in[1];
    const float* Wq   = (const float*)d_in[2];
    const float* Wkv  = (const float*)d_in[3];
    const float* Wc   = (const float*)d_in[4];
    const float* qn1  = (const float*)d_in[5];
    const float* kn1  = (const float*)d_in[6];
    const float* qn2  = (const float*)d_in[7];
    const float* kn2  = (const float*)d_in[8];
    const float* gn_w = (const float*)d_in[9];
    const float* gn_b = (const float*)d_in[10];
    const float* lmb  = (const float*)d_in[11];
    float* out = (float*)d_out;

    float *y;
    cudaGetSymbolAddress((void**)&y, g_y);

    __nv_bfloat16 *xq_hi, *xq_lo, *xkv_hi, *xkv_lo, *ybt_hi, *ybt_lo;
    __nv_bfloat16 *q1h, *q1l, *q2h, *q2l, *k1h, *k1l, *k2h, *k2l, *vhh, *vhl;
    cudaGetSymbolAddress((void**)&xq_hi,  g_xq_hi);
    cudaGetSymbolAddress((void**)&xq_lo,  g_xq_lo);
    cudaGetSymbolAddress((void**)&xkv_hi, g_xkv_hi);
    cudaGetSymbolAddress((void**)&xkv_lo, g_xkv_lo);
    cudaGetSymbolAddress((void**)&ybt_hi, g_ybt_hi);
    cudaGetSymbolAddress((void**)&ybt_lo, g_ybt_lo);
    cudaGetSymbolAddress((void**)&q1h, g_q1h);
    cudaGetSymbolAddress((void**)&q1l, g_q1l);
    cudaGetSymbolAddress((void**)&q2h, g_q2h);
    cudaGetSymbolAddress((void**)&q2l, g_q2l);
    cudaGetSymbolAddress((void**)&k1h, g_k1h);
    cudaGetSymbolAddress((void**)&k1l, g_k1l);
    cudaGetSymbolAddress((void**)&k2h, g_k2h);
    cudaGetSymbolAddress((void**)&k2l, g_k2l);
    cudaGetSymbolAddress((void**)&vhh, g_vhh);
    cudaGetSymbolAddress((void**)&vhl, g_vhl);

    const int M = B_ * TQ_;  // 4096

    cudaFuncSetAttribute(gemm_fw, cudaFuncAttributeMaxDynamicSharedMemorySize, GM_SMEM);
    cudaFuncSetAttribute(gemm_fw_rms, cudaFuncAttributeMaxDynamicSharedMemorySize, GM_SMEM);
    cudaFuncSetAttribute(flash_mma_kernel, cudaFuncAttributeMaxDynamicSharedMemorySize, FLASH_SMEM);

    // 0) split x_q and x_kv to bf16 hi/lo (single launch)
    {
        const int n4 = M * D_ / 4;
        split2_kernel<<<dim3(n4 / 256, 2), 256>>>(x_q, xq_hi, xq_lo,
                                                  x_kv, xkv_hi, xkv_lo, n4);
    }

    // 1) projections: GEMM + in-loop W transpose/split + fused RMS epilogue
    {
        RmsDst Pq;
        Pq.w0 = qn1; Pq.w1 = qn2;
        Pq.h0 = q1h; Pq.l0 = q1l;
        Pq.h1 = q2h; Pq.l1 = q2l;
        Pq.h2 = nullptr; Pq.l2 = nullptr;
        Pq.qscale = 0.125f;
        gemm_fw_rms<<<dim3(2 * D_ / 128, M / 128), 256, GM_SMEM>>>(
            xq_hi, xq_lo, Wq, Pq, M, 2 * D_, D_);

        RmsDst Pkv;
        Pkv.w0 = kn1; Pkv.w1 = kn2;
        Pkv.h0 = k1h; Pkv.l0 = k1l;
        Pkv.h1 = k2h; Pkv.l1 = k2l;
        Pkv.h2 = vhh; Pkv.l2 = vhl;
        Pkv.qscale = 1.0f;
        gemm_fw_rms<<<dim3(3 * D_ / 128, M / 128), 256, GM_SMEM>>>(
            xkv_hi, xkv_lo, Wkv, Pkv, M, 3 * D_, D_);
    }

    // 2) merged dual flash attention
    flash_mma_kernel<<<dim3(TQ_ / 128, H_, B_), 256, FLASH_SMEM>>>(
        q1h, q1l, q2h, q2l, k1h, k1l, k2h, k2l, vhh, vhl, lmb, y);

    // 3) fused GroupNorm (stats + apply + transpose + split)
    gn_fused_kernel<<<B_ * H_, 256>>>(y, gn_w, gn_b, ybt_hi, ybt_lo);

    // 4) output projection: GEMM + in-loop Wc transpose/split
    gemm_fw<<<dim3(D_ / 128, M / 128), 256, GM_SMEM>>>(
        ybt_hi, ybt_lo, Wc, out, M, D_, D_);
}

// round 13
// speedup vs baseline: 1.0784x; 1.0784x over previous
#include <cuda_runtime.h>
#include <cuda_bf16.h>
#include <math.h>
#include <stdint.h>

// Problem constants
#define B_    4
#define TQ_   1024
#define TKV_  1024
#define D_    1024
#define H_    16
#define HD_   64
#define EPS_  1e-5f

// ===========================================================================
// PTX helpers (baseline features only — compute_103 virtual arch safe)
// ===========================================================================
__device__ __forceinline__ uint32_t smem_to_u32(const void* smem_ptr) {
    uint32_t addr;
    asm("{ .reg .u64 tmp; cvta.to.shared.u64 tmp, %1; cvt.u32.u64 %0, tmp; }"
        : "=r"(addr) : "l"(smem_ptr));
    return addr;
}

__device__ __forceinline__ void cp_async16(uint32_t dst, const void* src) {
    asm volatile("cp.async.cg.shared.global [%0], [%1], 16;" :: "r"(dst), "l"(src));
}
#define CP_COMMIT() asm volatile("cp.async.commit_group;" ::: "memory")
#define CP_WAIT(n)  asm volatile("cp.async.wait_group %0;" :: "n"(n) : "memory")

__device__ __forceinline__ void ldsm_x4(uint32_t& r0, uint32_t& r1, uint32_t& r2,
                                        uint32_t& r3, uint32_t addr) {
    asm volatile("ldmatrix.sync.aligned.m8n8.x4.shared.b16 {%0,%1,%2,%3}, [%4];"
        : "=r"(r0), "=r"(r1), "=r"(r2), "=r"(r3) : "r"(addr));
}

__device__ __forceinline__ void ldsm_x4_t(uint32_t& r0, uint32_t& r1, uint32_t& r2,
                                          uint32_t& r3, uint32_t addr) {
    asm volatile("ldmatrix.sync.aligned.m8n8.x4.trans.shared.b16 {%0,%1,%2,%3}, [%4];"
        : "=r"(r0), "=r"(r1), "=r"(r2), "=r"(r3) : "r"(addr));
}

// D += A * B  (m16n8k16, bf16 inputs, fp32 accum)
__device__ __forceinline__ void mma16816(float* d, const uint32_t* a,
                                         uint32_t b0, uint32_t b1) {
    asm volatile(
        "mma.sync.aligned.m16n8k16.row.col.f32.bf16.bf16.f32 "
        "{%0,%1,%2,%3}, {%4,%5,%6,%7}, {%8,%9}, {%0,%1,%2,%3};"
        : "+f"(d[0]), "+f"(d[1]), "+f"(d[2]), "+f"(d[3])
        : "r"(a[0]), "r"(a[1]), "r"(a[2]), "r"(a[3]), "r"(b0), "r"(b1));
}

__device__ __forceinline__ uint32_t pack_bf16(float a, float b) {
    __nv_bfloat162 t = __floats2bfloat162_rn(a, b);
    return *reinterpret_cast<uint32_t*>(&t);
}

// ===========================================================================
// Device scratch
// ===========================================================================
__device__ float g_y     [B_ * H_ * TQ_  * HD_];

__device__ __nv_bfloat16 g_xq_hi [B_ * TQ_ * D_];
__device__ __nv_bfloat16 g_xq_lo [B_ * TQ_ * D_];
__device__ __nv_bfloat16 g_xkv_hi[B_ * TKV_ * D_];
__device__ __nv_bfloat16 g_xkv_lo[B_ * TKV_ * D_];
__device__ __nv_bfloat16 g_wqt_hi [2 * D_ * D_];
__device__ __nv_bfloat16 g_wqt_lo [2 * D_ * D_];
__device__ __nv_bfloat16 g_wkvt_hi[3 * D_ * D_];
__device__ __nv_bfloat16 g_wkvt_lo[3 * D_ * D_];
__device__ __nv_bfloat16 g_wct_hi [D_ * D_];
__device__ __nv_bfloat16 g_wct_lo [D_ * D_];
__device__ __nv_bfloat16 g_ybt_hi [B_ * TQ_ * D_];
__device__ __nv_bfloat16 g_ybt_lo [B_ * TQ_ * D_];

// bf16 hi/lo attention operands, (B,H,T,HD)
__device__ __nv_bfloat16 g_q1h[B_ * H_ * TQ_ * HD_];
__device__ __nv_bfloat16 g_q1l[B_ * H_ * TQ_ * HD_];
__device__ __nv_bfloat16 g_q2h[B_ * H_ * TQ_ * HD_];
__device__ __nv_bfloat16 g_q2l[B_ * H_ * TQ_ * HD_];
__device__ __nv_bfloat16 g_k1h[B_ * H_ * TKV_ * HD_];
__device__ __nv_bfloat16 g_k1l[B_ * H_ * TKV_ * HD_];
__device__ __nv_bfloat16 g_k2h[B_ * H_ * TKV_ * HD_];
__device__ __nv_bfloat16 g_k2l[B_ * H_ * TKV_ * HD_];
__device__ __nv_bfloat16 g_vhh[B_ * H_ * TKV_ * HD_];
__device__ __nv_bfloat16 g_vhl[B_ * H_ * TKV_ * HD_];

// ===========================================================================
// Split fp32 -> bf16 hi/lo (both x tensors in one launch; grid.y selects)
// ===========================================================================
__global__ void split2_kernel(const float* __restrict__ xa,
                              __nv_bfloat16* __restrict__ hia, __nv_bfloat16* __restrict__ loa,
                              const float* __restrict__ xb,
                              __nv_bfloat16* __restrict__ hib, __nv_bfloat16* __restrict__ lob,
                              int n4)
{
    const int i = blockIdx.x * blockDim.x + threadIdx.x;
    if (i >= n4) return;
    const float* x = blockIdx.y ? xb : xa;
    __nv_bfloat16* hi = blockIdx.y ? hib : hia;
    __nv_bfloat16* lo = blockIdx.y ? lob : loa;
    float4 v = ((const float4*)x)[i];
    float f[4] = {v.x, v.y, v.z, v.w};
    __nv_bfloat16 h[4], l[4];
    #pragma unroll
    for (int j = 0; j < 4; j++) {
        h[j] = __float2bfloat16_rn(f[j]);
        l[j] = __float2bfloat16_rn(f[j] - __bfloat162float(h[j]));
    }
    ((__nv_bfloat162*)hi)[2*i + 0] = __nv_bfloat162(h[0], h[1]);
    ((__nv_bfloat162*)hi)[2*i + 1] = __nv_bfloat162(h[2], h[3]);
    ((__nv_bfloat162*)lo)[2*i + 0] = __nv_bfloat162(l[0], l[1]);
    ((__nv_bfloat162*)lo)[2*i + 1] = __nv_bfloat162(l[2], l[3]);
}

// ===========================================================================
// Transpose + split: W [K,N] fp32 -> Wt_hi/lo [N,K] bf16 (K-major)
// ===========================================================================
__global__ void split_transpose_kernel(const float* __restrict__ W,
                                       __nv_bfloat16* __restrict__ hi,
                                       __nv_bfloat16* __restrict__ lo, int K, int N)
{
    __shared__ float t[32][33];
    const int n0 = blockIdx.x * 32, k0 = blockIdx.y * 32;
    #pragma unroll
    for (int dy = 0; dy < 32; dy += 8)
        t[threadIdx.y + dy][threadIdx.x] =
            W[(size_t)(k0 + threadIdx.y + dy) * N + n0 + threadIdx.x];
    __syncthreads();
    #pragma unroll
    for (int dy = 0; dy < 32; dy += 8) {
        const int n = n0 + threadIdx.y + dy, k = k0 + threadIdx.x;
        const float v = t[threadIdx.x][threadIdx.y + dy];
        const __nv_bfloat16 h = __float2bfloat16_rn(v);
        hi[(size_t)n * K + k] = h;
        lo[(size_t)n * K + k] = __float2bfloat16_rn(v - __bfloat162float(h));
    }
}

// ===========================================================================
// mma.sync bf16x3 GEMM (R9 design — pre-split operands; benched 937us total)
// ===========================================================================
#define SAST       40
#define GM_TILE_B  (128 * SAST * 2)
#define GM_STAGE_B (4 * GM_TILE_B)
#define GM_SMEM    (2 * GM_STAGE_B)       // 81920

__device__ __forceinline__ void gm_load_stage(
    uint32_t stage_base, const __nv_bfloat16* const* srcs, int k0, int K, int tid)
{
    #pragma unroll
    for (int t = 0; t < 4; t++) {
        const __nv_bfloat16* s = srcs[t] + k0;
        const uint32_t tb = stage_base + t * GM_TILE_B;
        #pragma unroll
        for (int i = 0; i < 2; i++) {
            const int idx = tid + i * 256;
            const int row = idx >> 2, c16 = idx & 3;
            cp_async16(tb + row * (SAST * 2) + c16 * 16,
                       s + (size_t)row * K + c16 * 8);
        }
    }
    CP_COMMIT();
}

__device__ __forceinline__ void gm_mainloop(
    uint32_t sb, const __nv_bfloat16* const* srcs, int K,
    int tid, int lane, int wm, int wn, float acc[4][4][4])
{
    const int nch = K >> 5;
    gm_load_stage(sb, srcs, 0, K, tid);

    const uint32_t lrow = (lane & 15);
    const uint32_t lcol16 = (lane >> 4) * 16;

    for (int c = 0; c < nch; c++) {
        if (c + 1 < nch) gm_load_stage(sb + ((c + 1) & 1) * GM_STAGE_B, srcs, (c + 1) << 5, K, tid);
        if (c + 1 < nch) { CP_WAIT(1); } else { CP_WAIT(0); }
        __syncthreads();

        const uint32_t st = sb + (c & 1) * GM_STAGE_B;
        #pragma unroll
        for (int ks = 0; ks < 2; ks++) {
            const uint32_t coff = lcol16 + ks * 32;
            uint32_t bh[2][4], bl[2][4];
            #pragma unroll
            for (int nt = 0; nt < 2; nt++) {
                const uint32_t baddr = st + 2 * GM_TILE_B
                    + (wn * 32 + nt * 16 + lrow) * (SAST * 2) + coff;
                ldsm_x4(bh[nt][0], bh[nt][1], bh[nt][2], bh[nt][3], baddr);
                ldsm_x4(bl[nt][0], bl[nt][1], bl[nt][2], bl[nt][3], baddr + GM_TILE_B);
            }
            #pragma unroll
            for (int mt = 0; mt < 4; mt++) {
                const uint32_t aaddr = st
                    + (wm * 64 + mt * 16 + lrow) * (SAST * 2) + coff;
                uint32_t ah[4], al[4];
                ldsm_x4(ah[0], ah[1], ah[2], ah[3], aaddr);
                ldsm_x4(al[0], al[1], al[2], al[3], aaddr + GM_TILE_B);
                #pragma unroll
                for (int nt = 0; nt < 2; nt++) {
                    #pragma unroll
                    for (int hh = 0; hh < 2; hh++) {
                        float* d = acc[mt][nt * 2 + hh];
                        uint32_t bfh0 = bh[nt][hh], bfh1 = bh[nt][hh + 2];
                        mma16816(d, ah, bfh0, bfh1);
                        mma16816(d, ah, bl[nt][hh], bl[nt][hh + 2]);
                        mma16816(d, al, bfh0, bfh1);
                    }
                }
            }
        }
        __syncthreads();
    }
}

// ---- plain epilogue (fp32 C) — out-projection ----
__global__ __launch_bounds__(256) void gemm_mma(
    const __nv_bfloat16* __restrict__ Ahi, const __nv_bfloat16* __restrict__ Alo,
    const __nv_bfloat16* __restrict__ Bhi, const __nv_bfloat16* __restrict__ Blo,
    float* __restrict__ C, int M, int N, int K)
{
    extern __shared__ __align__(128) char smem[];
    const uint32_t sb = smem_to_u32(smem);
    const int tid = threadIdx.x;
    const int lane = tid & 31;
    const int wid = tid >> 5;
    const int wm = wid & 1;
    const int wn = wid >> 1;
    const int bx = blockIdx.x, by = blockIdx.y;

    const __nv_bfloat16* srcs[4] = {
        Ahi + (size_t)(by * 128) * K, Alo + (size_t)(by * 128) * K,
        Bhi + (size_t)(bx * 128) * K, Blo + (size_t)(bx * 128) * K };

    float acc[4][4][4];
    #pragma unroll
    for (int a = 0; a < 4; a++)
        #pragma unroll
        for (int b = 0; b < 4; b++)
            #pragma unroll
            for (int c = 0; c < 4; c++) acc[a][b][c] = 0.f;

    gm_mainloop(sb, srcs, K, tid, lane, wm, wn, acc);

    #pragma unroll
    for (int mt = 0; mt < 4; mt++) {
        const int row0 = by * 128 + wm * 64 + mt * 16 + (lane >> 2);
        #pragma unroll
        for (int n8 = 0; n8 < 4; n8++) {
            const int col = bx * 128 + wn * 32 + n8 * 8 + (lane & 3) * 2;
            float2 o0 = make_float2(acc[mt][n8][0], acc[mt][n8][1]);
            float2 o1 = make_float2(acc[mt][n8][2], acc[mt][n8][3]);
            *(float2*)&C[(size_t)row0 * N + col]       = o0;
            *(float2*)&C[(size_t)(row0 + 8) * N + col] = o1;
        }
    }
}

// ---- RMS epilogue variant: fused RMSNorm + head-reshape + bf16 split ----
struct RmsDst {
    const float* w0;
    const float* w1;
    __nv_bfloat16 *h0, *l0;
    __nv_bfloat16 *h1, *l1;
    __nv_bfloat16 *h2, *l2;
    float qscale;
};

__global__ __launch_bounds__(256) void gemm_mma_rms(
    const __nv_bfloat16* __restrict__ Ahi, const __nv_bfloat16* __restrict__ Alo,
    const __nv_bfloat16* __restrict__ Bhi, const __nv_bfloat16* __restrict__ Blo,
    RmsDst P, int M, int N, int K)
{
    extern __shared__ __align__(128) char smem[];
    const uint32_t sb = smem_to_u32(smem);
    const int tid = threadIdx.x;
    const int lane = tid & 31;
    const int wid = tid >> 5;
    const int wm = wid & 1;
    const int wn = wid >> 1;
    const int bx = blockIdx.x, by = blockIdx.y;

    const __nv_bfloat16* srcs[4] = {
        Ahi + (size_t)(by * 128) * K, Alo + (size_t)(by * 128) * K,
        Bhi + (size_t)(bx * 128) * K, Blo + (size_t)(bx * 128) * K };

    float acc[4][4][4];
    #pragma unroll
    for (int a = 0; a < 4; a++)
        #pragma unroll
        for (int b = 0; b < 4; b++)
            #pragma unroll
            for (int c = 0; c < 4; c++) acc[a][b][c] = 0.f;

    gm_mainloop(sb, srcs, K, tid, lane, wm, wn, acc);

    // acc -> smem fp32 tile [128][132]
    float* sE = (float*)smem;
    #pragma unroll
    for (int mt = 0; mt < 4; mt++) {
        const int r0 = wm * 64 + mt * 16 + (lane >> 2);
        #pragma unroll
        for (int n8 = 0; n8 < 4; n8++) {
            const int c = wn * 32 + n8 * 8 + (lane & 3) * 2;
            *(float2*)&sE[r0 * 132 + c]       = make_float2(acc[mt][n8][0], acc[mt][n8][1]);
            *(float2*)&sE[(r0 + 8) * 132 + c] = make_float2(acc[mt][n8][2], acc[mt][n8][3]);
        }
    }
    __syncthreads();

    const int bq    = by >> 3;
    const int hloc  = lane >> 4;
    const int cg    = bx * 128 + hloc * 64;
    const int which = cg >> 10;
    const int hh    = (cg >> 6) & 15;
    const int d0    = (lane & 15) * 4;
    const bool donorm = (which < 2);
    const float* wptr = (which == 0) ? P.w0 : P.w1;
    float4 wv = make_float4(1.f, 1.f, 1.f, 1.f);
    if (donorm) wv = *(const float4*)&wptr[d0];
    __nv_bfloat16* dh = (which == 0) ? P.h0 : ((which == 1) ? P.h1 : P.h2);
    __nv_bfloat16* dl = (which == 0) ? P.l0 : ((which == 1) ? P.l1 : P.l2);
    const int w8 = wid * 16;

    #pragma unroll 4
    for (int i = 0; i < 16; i++) {
        const int r = w8 + i;
        float4 v = *(const float4*)&sE[r * 132 + lane * 4];
        float ss = v.x * v.x + v.y * v.y + v.z * v.z + v.w * v.w;
        ss += __shfl_xor_sync(0xffffffffu, ss, 1);
        ss += __shfl_xor_sync(0xffffffffu, ss, 2);
        ss += __shfl_xor_sync(0xffffffffu, ss, 4);
        ss += __shfl_xor_sync(0xffffffffu, ss, 8);
        const float rr = donorm ? rsqrtf(ss * (1.0f / 64.0f) + EPS_) * P.qscale : 1.f;
        const float f0 = v.x * rr * wv.x;
        const float f1 = v.y * rr * wv.y;
        const float f2 = v.z * rr * wv.z;
        const float f3 = v.w * rr * wv.w;
        const __nv_bfloat16 b0 = __float2bfloat16_rn(f0);
        const __nv_bfloat16 b1 = __float2bfloat16_rn(f1);
        const __nv_bfloat16 b2 = __float2bfloat16_rn(f2);
        const __nv_bfloat16 b3 = __float2bfloat16_rn(f3);
        const uint32_t H01 = pack_bf16(f0, f1);
        const uint32_t H23 = pack_bf16(f2, f3);
        const uint32_t L01 = pack_bf16(f0 - __bfloat162float(b0), f1 - __bfloat162float(b1));
        const uint32_t L23 = pack_bf16(f2 - __bfloat162float(b2), f3 - __bfloat162float(b3));
        const int t = (by & 7) * 128 + r;
        const size_t idx = ((((size_t)bq * 16 + hh) * 1024) + t) * 64 + d0;
        *(uint2*)&dh[idx] = make_uint2(H01, H23);
        *(uint2*)&dl[idx] = make_uint2(L01, L23);
    }
}

// ===========================================================================
// Dual flash attention, mma.sync bf16x3 — SMALL-CTA version for 2 CTAs/SM.
// 128 threads (4 warps x 16 q rows = 64-row q tile); 32-row kv tiles.
// smem: 4 Q tiles (64x144B) + double-buffered 6-tile KV stages (32x144B).
// Total 92160 B -> 2 CTAs/SM; cross-CTA overlap hides softmax under MMA.
// ===========================================================================
#define FSTR_B    144
#define FQ_TILE   (64 * FSTR_B)             // 9216
#define FKV_TILE  (32 * FSTR_B)             // 4608
#define FKV_STAGE (6 * FKV_TILE)            // 27648
#define FLASH_SMEM (4 * FQ_TILE + 2 * FKV_STAGE)   // 92160

__device__ __forceinline__ void flash_load_kv6(
    uint32_t dst, const __nv_bfloat16* const* srcs, int kt, int tid)
{
    #pragma unroll
    for (int i = 0; i < 12; i++) {
        const int idx = tid + i * 128;        // 1536 chunks of 16B
        const int t = idx >> 8;               // 256 chunks per tensor
        const int rem = idx & 255;
        const int row = rem >> 3, c = rem & 7;
        cp_async16(dst + t * FKV_TILE + row * FSTR_B + c * 16,
                   srcs[t] + ((size_t)(kt * 32 + row)) * HD_ + c * 8);
    }
}

__device__ __forceinline__ void softmax_step4(float s[4][4], float m[2], float l[2],
                                              float o[8][4])
{
    float mx0 = -1e30f, mx1 = -1e30f;
    #pragma unroll
    for (int j = 0; j < 4; j++) {
        mx0 = fmaxf(mx0, fmaxf(s[j][0], s[j][1]));
        mx1 = fmaxf(mx1, fmaxf(s[j][2], s[j][3]));
    }
    mx0 = fmaxf(mx0, __shfl_xor_sync(0xffffffffu, mx0, 1));
    mx0 = fmaxf(mx0, __shfl_xor_sync(0xffffffffu, mx0, 2));
    mx1 = fmaxf(mx1, __shfl_xor_sync(0xffffffffu, mx1, 1));
    mx1 = fmaxf(mx1, __shfl_xor_sync(0xffffffffu, mx1, 2));
    const float mn0 = fmaxf(m[0], mx0), mn1 = fmaxf(m[1], mx1);
    const float a0 = __expf(m[0] - mn0), a1 = __expf(m[1] - mn1);
    m[0] = mn0; m[1] = mn1;
    float ps0 = 0.f, ps1 = 0.f;
    #pragma unroll
    for (int j = 0; j < 4; j++) {
        s[j][0] = __expf(s[j][0] - mn0);
        s[j][1] = __expf(s[j][1] - mn0);
        s[j][2] = __expf(s[j][2] - mn1);
        s[j][3] = __expf(s[j][3] - mn1);
        ps0 += s[j][0] + s[j][1];
        ps1 += s[j][2] + s[j][3];
    }
    ps0 += __shfl_xor_sync(0xffffffffu, ps0, 1);
    ps0 += __shfl_xor_sync(0xffffffffu, ps0, 2);
    ps1 += __shfl_xor_sync(0xffffffffu, ps1, 1);
    ps1 += __shfl_xor_sync(0xffffffffu, ps1, 2);
    l[0] = l[0] * a0 + ps0;
    l[1] = l[1] * a1 + ps1;
    #pragma unroll
    for (int j = 0; j < 8; j++) {
        o[j][0] *= a0; o[j][1] *= a0;
        o[j][2] *= a1; o[j][3] *= a1;
    }
}

__device__ __forceinline__ void build_p4(const float s[4][4],
                                         uint32_t ph[2][4], uint32_t pl[2][4])
{
    #pragma unroll
    for (int kc = 0; kc < 2; kc++) {
        const int j0 = 2 * kc, j1 = 2 * kc + 1;
        ph[kc][0] = pack_bf16(s[j0][0], s[j0][1]);
        ph[kc][1] = pack_bf16(s[j0][2], s[j0][3]);
        ph[kc][2] = pack_bf16(s[j1][0], s[j1][1]);
        ph[kc][3] = pack_bf16(s[j1][2], s[j1][3]);
        float r00 = s[j0][0] - __bfloat162float(__float2bfloat16_rn(s[j0][0]));
        float r01 = s[j0][1] - __bfloat162float(__float2bfloat16_rn(s[j0][1]));
        float r02 = s[j0][2] - __bfloat162float(__float2bfloat16_rn(s[j0][2]));
        float r03 = s[j0][3] - __bfloat162float(__float2bfloat16_rn(s[j0][3]));
        float r10 = s[j1][0] - __bfloat162float(__float2bfloat16_rn(s[j1][0]));
        float r11 = s[j1][1] - __bfloat162float(__float2bfloat16_rn(s[j1][1]));
        float r12 = s[j1][2] - __bfloat162float(__float2bfloat16_rn(s[j1][2]));
        float r13 = s[j1][3] - __bfloat162float(__float2bfloat16_rn(s[j1][3]));
        pl[kc][0] = pack_bf16(r00, r01);
        pl[kc][1] = pack_bf16(r02, r03);
        pl[kc][2] = pack_bf16(r10, r11);
        pl[kc][3] = pack_bf16(r12, r13);
    }
}

__device__ __forceinline__ void pv_step4(float o[8][4], const uint32_t ph[2][4],
                                         const uint32_t pl[2][4], uint32_t st,
                                         uint32_t lrow16)
{
    #pragma unroll
    for (int kc = 0; kc < 2; kc++) {
        #pragma unroll
        for (int hg = 0; hg < 4; hg++) {
            const uint32_t addr = st + kc * 16 * FSTR_B + lrow16 + hg * 32;
            uint32_t vh0, vh1, vh2, vh3, vl0, vl1, vl2, vl3;
            ldsm_x4_t(vh0, vh1, vh2, vh3, addr + 4 * FKV_TILE);
            ldsm_x4_t(vl0, vl1, vl2, vl3, addr + 5 * FKV_TILE);
            mma16816(o[2 * hg],     ph[kc], vh0, vh1);
            mma16816(o[2 * hg],     pl[kc], vh0, vh1);
            mma16816(o[2 * hg],     ph[kc], vl0, vl1);
            mma16816(o[2 * hg + 1], ph[kc], vh2, vh3);
            mma16816(o[2 * hg + 1], pl[kc], vh2, vh3);
            mma16816(o[2 * hg + 1], ph[kc], vl2, vl3);
        }
    }
}

__global__ __launch_bounds__(128, 2) void flash_mma_kernel(
    const __nv_bfloat16* __restrict__ q1h, const __nv_bfloat16* __restrict__ q1l,
    const __nv_bfloat16* __restrict__ q2h, const __nv_bfloat16* __restrict__ q2l,
    const __nv_bfloat16* __restrict__ k1h, const __nv_bfloat16* __restrict__ k1l,
    const __nv_bfloat16* __restrict__ k2h, const __nv_bfloat16* __restrict__ k2l,
    const __nv_bfloat16* __restrict__ vhh, const __nv_bfloat16* __restrict__ vhl,
    const float* __restrict__ lmb, float* __restrict__ y)
{
    extern __shared__ __align__(128) char smem[];
    const uint32_t sb = smem_to_u32(smem);
    const uint32_t sQ = sb, sKV = sb + 4 * FQ_TILE;
    const int tid = threadIdx.x;
    const int lane = tid & 31;
    const int w = tid >> 5;                    // 0..3
    const int qt = blockIdx.x, h = blockIdx.y, b = blockIdx.z;
    const int bh = b * H_ + h;
    const size_t off = (size_t)bh * TQ_ * HD_;

    const __nv_bfloat16* kvsrc[6] = {
        k1h + off, k1l + off, k2h + off, k2l + off, vhh + off, vhl + off };
    const __nv_bfloat16* qsrc[4] = {
        q1h + off, q1l + off, q2h + off, q2l + off };

    // stage Q (4 tiles of 64 rows) + KV tiles 0 and 1
    #pragma unroll
    for (int i = 0; i < 16; i++) {
        const int idx = tid + i * 128;          // 2048 chunks
        const int ts = idx >> 9;                // 512 chunks per tensor
        const int rem = idx & 511;
        const int row = rem >> 3, c = rem & 7;
        cp_async16(sQ + ts * FQ_TILE + row * FSTR_B + c * 16,
                   qsrc[ts] + ((size_t)(qt * 64 + row)) * HD_ + c * 8);
    }
    flash_load_kv6(sKV, kvsrc, 0, tid);
    CP_COMMIT();
    flash_load_kv6(sKV + FKV_STAGE, kvsrc, 1, tid);
    CP_COMMIT();

    float o1[8][4], o2[8][4];
    float m1[2] = {-1e30f, -1e30f}, l1[2] = {0.f, 0.f};
    float m2[2] = {-1e30f, -1e30f}, l2[2] = {0.f, 0.f};
    #pragma unroll
    for (int j = 0; j < 8; j++)
        #pragma unroll
        for (int q = 0; q < 4; q++) { o1[j][q] = 0.f; o2[j][q] = 0.f; }

    CP_WAIT(1);
    __syncthreads();

    const uint32_t qrow = (w * 16 + (lane & 15)) * FSTR_B + (lane >> 4) * 16;
    const uint32_t lrow16 = (lane & 15) * FSTR_B + (lane >> 4) * 16;

    // Q1 fragments register-resident
    uint32_t q1hf[4][4], q1lf[4][4];
    #pragma unroll
    for (int kc = 0; kc < 4; kc++) {
        ldsm_x4(q1hf[kc][0], q1hf[kc][1], q1hf[kc][2], q1hf[kc][3],
                sQ + qrow + kc * 32);
        ldsm_x4(q1lf[kc][0], q1lf[kc][1], q1lf[kc][2], q1lf[kc][3],
                sQ + FQ_TILE + qrow + kc * 32);
    }

    for (int t = 0; t < 32; t++) {
        if (t > 0) {
            if (t + 1 < 32) { CP_WAIT(1); } else { CP_WAIT(0); }
            __syncthreads();
        }
        const uint32_t st = sKV + (t & 1) * FKV_STAGE;

        // ======== attention 1 ========
        {
            float s[4][4];
            #pragma unroll
            for (int j = 0; j < 4; j++)
                #pragma unroll
                for (int q = 0; q < 4; q++) s[j][q] = 0.f;

            #pragma unroll
            for (int kc = 0; kc < 4; kc++) {
                #pragma unroll
                for (int g = 0; g < 2; g++) {
                    const uint32_t addr = st + g * 16 * FSTR_B + lrow16 + kc * 32;
                    uint32_t h0, h1, h2, h3, l0, l1r, l2r, l3;
                    ldsm_x4(h0, h1, h2, h3, addr);
                    ldsm_x4(l0, l1r, l2r, l3, addr + FKV_TILE);
                    mma16816(s[2 * g],     q1hf[kc], h0, h2);
                    mma16816(s[2 * g],     q1hf[kc], l0, l2r);
                    mma16816(s[2 * g],     q1lf[kc], h0, h2);
                    mma16816(s[2 * g + 1], q1hf[kc], h1, h3);
                    mma16816(s[2 * g + 1], q1hf[kc], l1r, l3);
                    mma16816(s[2 * g + 1], q1lf[kc], h1, h3);
                }
            }
            softmax_step4(s, m1, l1, o1);
            uint32_t ph[2][4], pl[2][4];
            build_p4(s, ph, pl);
            pv_step4(o1, ph, pl, st, lrow16);
        }

        // ======== attention 2 (Q2 frags re-ldsm'd) ========
        {
            float s[4][4];
            #pragma unroll
            for (int j = 0; j < 4; j++)
                #pragma unroll
                for (int q = 0; q < 4; q++) s[j][q] = 0.f;

            #pragma unroll
            for (int kc = 0; kc < 4; kc++) {
                uint32_t qh[4], ql[4];
                ldsm_x4(qh[0], qh[1], qh[2], qh[3], sQ + 2 * FQ_TILE + qrow + kc * 32);
                ldsm_x4(ql[0], ql[1], ql[2], ql[3], sQ + 3 * FQ_TILE + qrow + kc * 32);
                #pragma unroll
                for (int g = 0; g < 2; g++) {
                    const uint32_t addr = st + 2 * FKV_TILE + g * 16 * FSTR_B + lrow16 + kc * 32;
                    uint32_t h0, h1, h2, h3, l0, l1r, l2r, l3;
                    ldsm_x4(h0, h1, h2, h3, addr);
                    ldsm_x4(l0, l1r, l2r, l3, addr + FKV_TILE);
                    mma16816(s[2 * g],     qh, h0, h2);
                    mma16816(s[2 * g],     qh, l0, l2r);
                    mma16816(s[2 * g],     ql, h0, h2);
                    mma16816(s[2 * g + 1], qh, h1, h3);
                    mma16816(s[2 * g + 1], qh, l1r, l3);
                    mma16816(s[2 * g + 1], ql, h1, h3);
                }
            }
            softmax_step4(s, m2, l2, o2);
            uint32_t ph[2][4], pl[2][4];
            build_p4(s, ph, pl);
            pv_step4(o2, ph, pl, st, lrow16);
        }

        __syncthreads();
        if (t + 2 < 32) {
            flash_load_kv6(st, kvsrc, t + 2, tid);
            CP_COMMIT();
        }
    }

    // epilogue
    const float cmul = log1pf(__expf(lmb[h]));
    const int r0 = lane >> 2, cb = (lane & 3) * 2;
    const float il10 = 1.f / l1[0], il11 = 1.f / l1[1];
    const float il20 = cmul / l2[0], il21 = cmul / l2[1];
    const size_t ybase = off + (size_t)(qt * 64 + w * 16) * HD_;
    #pragma unroll
    for (int j = 0; j < 8; j++) {
        float2 v0 = make_float2(o1[j][0] * il10 - o2[j][0] * il20,
                                o1[j][1] * il10 - o2[j][1] * il20);
        float2 v1 = make_float2(o1[j][2] * il11 - o2[j][2] * il21,
                                o1[j][3] * il11 - o2[j][3] * il21);
        *(float2*)&y[ybase + (size_t)r0 * HD_ + j * 8 + cb]       = v0;
        *(float2*)&y[ybase + (size_t)(r0 + 8) * HD_ + j * 8 + cb] = v1;
    }
}

// ===========================================================================
// Merged GroupNorm: stats + apply + transpose + bf16 split, one block per (b,h)
// ===========================================================================
__global__ void gn_fused_kernel(const float* __restrict__ y,
                                const float* __restrict__ gw, const float* __restrict__ gb,
                                __nv_bfloat16* __restrict__ hi, __nv_bfloat16* __restrict__ lo)
{
    __shared__ float rs[256], rq[256];
    __shared__ float s_mu, s_rstd;
    const int bh = blockIdx.x, tid = threadIdx.x;
    const int b = bh >> 4, h = bh & 15;
    const float* p = y + (size_t)bh * TQ_ * HD_;

    float s = 0.f, q = 0.f;
    for (int i = tid * 4; i < TQ_ * HD_; i += 256 * 4) {
        float4 v = *(const float4*)(p + i);
        s += v.x + v.y + v.z + v.w;
        q += v.x * v.x + v.y * v.y + v.z * v.z + v.w * v.w;
    }
    rs[tid] = s; rq[tid] = q;
    __syncthreads();
    for (int o = 128; o; o >>= 1) {
        if (tid < o) { rs[tid] += rs[tid + o]; rq[tid] += rq[tid + o]; }
        __syncthreads();
    }
    if (tid == 0) {
        const float inv = 1.f / (float)(TQ_ * HD_);
        const float mu = rs[0] * inv;
        const float var = rq[0] * inv - mu * mu;
        s_mu = mu;
        s_rstd = rsqrtf(var + EPS_);
    }
    __syncthreads();
    const float mu = s_mu, rstd = s_rstd;

    for (int i = tid; i < TQ_ * HD_ / 4; i += 256) {
        const int t  = i >> 4;
        const int dd = (i & 15) * 4;
        float4 v = *(const float4*)(p + (size_t)t * HD_ + dd);
        float4 w = *(const float4*)&gw[h * 64 + dd];
        float4 bb = *(const float4*)&gb[h * 64 + dd];
        float f0 = (v.x - mu) * rstd * w.x + bb.x;
        float f1 = (v.y - mu) * rstd * w.y + bb.y;
        float f2 = (v.z - mu) * rstd * w.z + bb.z;
        float f3 = (v.w - mu) * rstd * w.w + bb.w;
        const __nv_bfloat16 b0 = __float2bfloat16_rn(f0);
        const __nv_bfloat16 b1 = __float2bfloat16_rn(f1);
        const __nv_bfloat16 b2 = __float2bfloat16_rn(f2);
        const __nv_bfloat16 b3 = __float2bfloat16_rn(f3);
        const size_t idx = ((size_t)(b * 1024 + t)) * 1024 + h * 64 + dd;
        *(uint2*)&hi[idx] = make_uint2(pack_bf16(f0, f1), pack_bf16(f2, f3));
        *(uint2*)&lo[idx] = make_uint2(
            pack_bf16(f0 - __bfloat162float(b0), f1 - __bfloat162float(b1)),
            pack_bf16(f2 - __bfloat162float(b2), f3 - __bfloat162float(b3)));
    }
}

// ===========================================================================
// Launch
// ===========================================================================
extern "C" void kernel_launch(void* const* d_in, const int* in_sizes, int n_in,
                              void* d_out, int out_size)
{
    const float* x_q  = (const float*)d_in[0];
    const float* x_kv = (const float*)d_in[1];
    const float* Wq   = (const float*)d_in[2];
    const float* Wkv  = (const float*)d_in[3];
    const float* Wc   = (const float*)d_in[4];
    const float* qn1  = (const float*)d_in[5];
    const float* kn1  = (const float*)d_in[6];
    const float* qn2  = (const float*)d_in[7];
    const float* kn2  = (const float*)d_in[8];
    const float* gn_w = (const float*)d_in[9];
    const float* gn_b = (const float*)d_in[10];
    const float* lmb  = (const float*)d_in[11];
    float* out = (float*)d_out;

    float *y;
    cudaGetSymbolAddress((void**)&y, g_y);

    __nv_bfloat16 *xq_hi, *xq_lo, *xkv_hi, *xkv_lo;
    __nv_bfloat16 *wqt_hi, *wqt_lo, *wkvt_hi, *wkvt_lo, *wct_hi, *wct_lo;
    __nv_bfloat16 *ybt_hi, *ybt_lo;
    __nv_bfloat16 *q1h, *q1l, *q2h, *q2l, *k1h, *k1l, *k2h, *k2l, *vhh, *vhl;
    cudaGetSymbolAddress((void**)&xq_hi,   g_xq_hi);
    cudaGetSymbolAddress((void**)&xq_lo,   g_xq_lo);
    cudaGetSymbolAddress((void**)&xkv_hi,  g_xkv_hi);
    cudaGetSymbolAddress((void**)&xkv_lo,  g_xkv_lo);
    cudaGetSymbolAddress((void**)&wqt_hi,  g_wqt_hi);
    cudaGetSymbolAddress((void**)&wqt_lo,  g_wqt_lo);
    cudaGetSymbolAddress((void**)&wkvt_hi, g_wkvt_hi);
    cudaGetSymbolAddress((void**)&wkvt_lo, g_wkvt_lo);
    cudaGetSymbolAddress((void**)&wct_hi,  g_wct_hi);
    cudaGetSymbolAddress((void**)&wct_lo,  g_wct_lo);
    cudaGetSymbolAddress((void**)&ybt_hi,  g_ybt_hi);
    cudaGetSymbolAddress((void**)&ybt_lo,  g_ybt_lo);
    cudaGetSymbolAddress((void**)&q1h, g_q1h);
    cudaGetSymbolAddress((void**)&q1l, g_q1l);
    cudaGetSymbolAddress((void**)&q2h, g_q2h);
    cudaGetSymbolAddress((void**)&q2l, g_q2l);
    cudaGetSymbolAddress((void**)&k1h, g_k1h);
    cudaGetSymbolAddress((void**)&k1l, g_k1l);
    cudaGetSymbolAddress((void**)&k2h, g_k2h);
    cudaGetSymbolAddress((void**)&k2l, g_k2l);
    cudaGetSymbolAddress((void**)&vhh, g_vhh);
    cudaGetSymbolAddress((void**)&vhl, g_vhl);

    const int M = B_ * TQ_;  // 4096

    cudaFuncSetAttribute(gemm_mma, cudaFuncAttributeMaxDynamicSharedMemorySize, GM_SMEM);
    cudaFuncSetAttribute(gemm_mma_rms, cudaFuncAttributeMaxDynamicSharedMemorySize, GM_SMEM);
    cudaFuncSetAttribute(flash_mma_kernel, cudaFuncAttributeMaxDynamicSharedMemorySize, FLASH_SMEM);

    // 0) split operands to bf16 hi/lo
    {
        const int n4 = M * D_ / 4;
        split2_kernel<<<dim3(n4 / 256, 2), 256>>>(x_q, xq_hi, xq_lo,
                                                  x_kv, xkv_hi, xkv_lo, n4);
        split_transpose_kernel<<<dim3(2 * D_ / 32, D_ / 32), dim3(32, 8)>>>(Wq,  wqt_hi,  wqt_lo,  D_, 2 * D_);
        split_transpose_kernel<<<dim3(3 * D_ / 32, D_ / 32), dim3(32, 8)>>>(Wkv, wkvt_hi, wkvt_lo, D_, 3 * D_);
        split_transpose_kernel<<<dim3(D_ / 32, D_ / 32),     dim3(32, 8)>>>(Wc,  wct_hi,  wct_lo,  D_, D_);
    }

    // 1) projections with fused RMSNorm + reshape + split (mma.sync bf16x3)
    {
        RmsDst Pq;
        Pq.w0 = qn1; Pq.w1 = qn2;
        Pq.h0 = q1h; Pq.l0 = q1l;
        Pq.h1 = q2h; Pq.l1 = q2l;
        Pq.h2 = nullptr; Pq.l2 = nullptr;
        Pq.qscale = 0.125f;
        gemm_mma_rms<<<dim3(2 * D_ / 128, M / 128), 256, GM_SMEM>>>(
            xq_hi, xq_lo, wqt_hi, wqt_lo, Pq, M, 2 * D_, D_);

        RmsDst Pkv;
        Pkv.w0 = kn1; Pkv.w1 = kn2;
        Pkv.h0 = k1h; Pkv.l0 = k1l;
        Pkv.h1 = k2h; Pkv.l1 = k2l;
        Pkv.h2 = vhh; Pkv.l2 = vhl;
        Pkv.qscale = 1.0f;
        gemm_mma_rms<<<dim3(3 * D_ / 128, M / 128), 256, GM_SMEM>>>(
            xkv_hi, xkv_lo, wkvt_hi, wkvt_lo, Pkv, M, 3 * D_, D_);
    }

    // 2) merged dual flash attention (small CTA, 2 CTAs/SM)
    flash_mma_kernel<<<dim3(TQ_ / 64, H_, B_), 128, FLASH_SMEM>>>(
        q1h, q1l, q2h, q2l, k1h, k1l, k2h, k2l, vhh, vhl, lmb, y);

    // 3) fused GroupNorm (stats + apply + transpose + split)
    gn_fused_kernel<<<B_ * H_, 256>>>(y, gn_w, gn_b, ybt_hi, ybt_lo);

    // 4) output projection (mma.sync bf16x3)
    gemm_mma<<<dim3(D_ / 128, M / 128), 256, GM_SMEM>>>(ybt_hi, ybt_lo, wct_hi, wct_lo, out, M, D_, D_);
}

// round 15
// speedup vs baseline: 1.0975x; 1.0177x over previous
#include <cuda_runtime.h>
#include <cuda_bf16.h>
#include <math.h>
#include <stdint.h>

// Problem constants
#define B_    4
#define TQ_   1024
#define TKV_  1024
#define D_    1024
#define H_    16
#define HD_   64
#define EPS_  1e-5f

// ===========================================================================
// PTX helpers (baseline features only — compute_103 virtual arch safe)
// ===========================================================================
__device__ __forceinline__ uint32_t smem_to_u32(const void* smem_ptr) {
    uint32_t addr;
    asm("{ .reg .u64 tmp; cvta.to.shared.u64 tmp, %1; cvt.u32.u64 %0, tmp; }"
        : "=r"(addr) : "l"(smem_ptr));
    return addr;
}

__device__ __forceinline__ void cp_async16(uint32_t dst, const void* src) {
    asm volatile("cp.async.cg.shared.global [%0], [%1], 16;" :: "r"(dst), "l"(src));
}
#define CP_COMMIT() asm volatile("cp.async.commit_group;" ::: "memory")
#define CP_WAIT(n)  asm volatile("cp.async.wait_group %0;" :: "n"(n) : "memory")

__device__ __forceinline__ void ldsm_x4(uint32_t& r0, uint32_t& r1, uint32_t& r2,
                                        uint32_t& r3, uint32_t addr) {
    asm volatile("ldmatrix.sync.aligned.m8n8.x4.shared.b16 {%0,%1,%2,%3}, [%4];"
        : "=r"(r0), "=r"(r1), "=r"(r2), "=r"(r3) : "r"(addr));
}

__device__ __forceinline__ void ldsm_x4_t(uint32_t& r0, uint32_t& r1, uint32_t& r2,
                                          uint32_t& r3, uint32_t addr) {
    asm volatile("ldmatrix.sync.aligned.m8n8.x4.trans.shared.b16 {%0,%1,%2,%3}, [%4];"
        : "=r"(r0), "=r"(r1), "=r"(r2), "=r"(r3) : "r"(addr));
}

// D += A * B  (m16n8k16, bf16 inputs, fp32 accum)
__device__ __forceinline__ void mma16816(float* d, const uint32_t* a,
                                         uint32_t b0, uint32_t b1) {
    asm volatile(
        "mma.sync.aligned.m16n8k16.row.col.f32.bf16.bf16.f32 "
        "{%0,%1,%2,%3}, {%4,%5,%6,%7}, {%8,%9}, {%0,%1,%2,%3};"
        : "+f"(d[0]), "+f"(d[1]), "+f"(d[2]), "+f"(d[3])
        : "r"(a[0]), "r"(a[1]), "r"(a[2]), "r"(a[3]), "r"(b0), "r"(b1));
}

__device__ __forceinline__ uint32_t pack_bf16(float a, float b) {
    __nv_bfloat162 t = __floats2bfloat162_rn(a, b);
    return *reinterpret_cast<uint32_t*>(&t);
}

// ===========================================================================
// Device scratch
// ===========================================================================
__device__ float g_y     [B_ * H_ * TQ_  * HD_];

__device__ __nv_bfloat16 g_xq_hi [B_ * TQ_ * D_];
__device__ __nv_bfloat16 g_xq_lo [B_ * TQ_ * D_];
__device__ __nv_bfloat16 g_xkv_hi[B_ * TKV_ * D_];
__device__ __nv_bfloat16 g_xkv_lo[B_ * TKV_ * D_];
__device__ __nv_bfloat16 g_wqt_hi [2 * D_ * D_];
__device__ __nv_bfloat16 g_wqt_lo [2 * D_ * D_];
__device__ __nv_bfloat16 g_wkvt_hi[3 * D_ * D_];
__device__ __nv_bfloat16 g_wkvt_lo[3 * D_ * D_];
__device__ __nv_bfloat16 g_wct_hi [D_ * D_];
__device__ __nv_bfloat16 g_wct_lo [D_ * D_];
__device__ __nv_bfloat16 g_ybt_hi [B_ * TQ_ * D_];
__device__ __nv_bfloat16 g_ybt_lo [B_ * TQ_ * D_];

// bf16 hi/lo attention operands, (B,H,T,HD)
__device__ __nv_bfloat16 g_q1h[B_ * H_ * TQ_ * HD_];
__device__ __nv_bfloat16 g_q1l[B_ * H_ * TQ_ * HD_];
__device__ __nv_bfloat16 g_q2h[B_ * H_ * TQ_ * HD_];
__device__ __nv_bfloat16 g_q2l[B_ * H_ * TQ_ * HD_];
__device__ __nv_bfloat16 g_k1h[B_ * H_ * TKV_ * HD_];
__device__ __nv_bfloat16 g_k1l[B_ * H_ * TKV_ * HD_];
__device__ __nv_bfloat16 g_k2h[B_ * H_ * TKV_ * HD_];
__device__ __nv_bfloat16 g_k2l[B_ * H_ * TKV_ * HD_];
__device__ __nv_bfloat16 g_vhh[B_ * H_ * TKV_ * HD_];
__device__ __nv_bfloat16 g_vhl[B_ * H_ * TKV_ * HD_];

// ===========================================================================
// Split fp32 -> bf16 hi/lo (both x tensors in one launch; grid.y selects)
// ===========================================================================
__global__ void split2_kernel(const float* __restrict__ xa,
                              __nv_bfloat16* __restrict__ hia, __nv_bfloat16* __restrict__ loa,
                              const float* __restrict__ xb,
                              __nv_bfloat16* __restrict__ hib, __nv_bfloat16* __restrict__ lob,
                              int n4)
{
    const int i = blockIdx.x * blockDim.x + threadIdx.x;
    if (i >= n4) return;
    const float* x = blockIdx.y ? xb : xa;
    __nv_bfloat16* hi = blockIdx.y ? hib : hia;
    __nv_bfloat16* lo = blockIdx.y ? lob : loa;
    float4 v = ((const float4*)x)[i];
    float f[4] = {v.x, v.y, v.z, v.w};
    __nv_bfloat16 h[4], l[4];
    #pragma unroll
    for (int j = 0; j < 4; j++) {
        h[j] = __float2bfloat16_rn(f[j]);
        l[j] = __float2bfloat16_rn(f[j] - __bfloat162float(h[j]));
    }
    ((__nv_bfloat162*)hi)[2*i + 0] = __nv_bfloat162(h[0], h[1]);
    ((__nv_bfloat162*)hi)[2*i + 1] = __nv_bfloat162(h[2], h[3]);
    ((__nv_bfloat162*)lo)[2*i + 0] = __nv_bfloat162(l[0], l[1]);
    ((__nv_bfloat162*)lo)[2*i + 1] = __nv_bfloat162(l[2], l[3]);
}

// ===========================================================================
// Transpose + split: W [K,N] fp32 -> Wt_hi/lo [N,K] bf16 (K-major)
// ===========================================================================
__global__ void split_transpose_kernel(const float* __restrict__ W,
                                       __nv_bfloat16* __restrict__ hi,
                                       __nv_bfloat16* __restrict__ lo, int K, int N)
{
    __shared__ float t[32][33];
    const int n0 = blockIdx.x * 32, k0 = blockIdx.y * 32;
    #pragma unroll
    for (int dy = 0; dy < 32; dy += 8)
        t[threadIdx.y + dy][threadIdx.x] =
            W[(size_t)(k0 + threadIdx.y + dy) * N + n0 + threadIdx.x];
    __syncthreads();
    #pragma unroll
    for (int dy = 0; dy < 32; dy += 8) {
        const int n = n0 + threadIdx.y + dy, k = k0 + threadIdx.x;
        const float v = t[threadIdx.x][threadIdx.y + dy];
        const __nv_bfloat16 h = __float2bfloat16_rn(v);
        hi[(size_t)n * K + k] = h;
        lo[(size_t)n * K + k] = __float2bfloat16_rn(v - __bfloat162float(h));
    }
}

// ===========================================================================
// mma.sync bf16x3 GEMM (R9 design — pre-split operands)
// ===========================================================================
#define SAST       40
#define GM_TILE_B  (128 * SAST * 2)
#define GM_STAGE_B (4 * GM_TILE_B)
#define GM_SMEM    (2 * GM_STAGE_B)       // 81920

__device__ __forceinline__ void gm_load_stage(
    uint32_t stage_base, const __nv_bfloat16* const* srcs, int k0, int K, int tid)
{
    #pragma unroll
    for (int t = 0; t < 4; t++) {
        const __nv_bfloat16* s = srcs[t] + k0;
        const uint32_t tb = stage_base + t * GM_TILE_B;
        #pragma unroll
        for (int i = 0; i < 2; i++) {
            const int idx = tid + i * 256;
            const int row = idx >> 2, c16 = idx & 3;
            cp_async16(tb + row * (SAST * 2) + c16 * 16,
                       s + (size_t)row * K + c16 * 8);
        }
    }
    CP_COMMIT();
}

__device__ __forceinline__ void gm_mainloop(
    uint32_t sb, const __nv_bfloat16* const* srcs, int K,
    int tid, int lane, int wm, int wn, float acc[4][4][4])
{
    const int nch = K >> 5;
    gm_load_stage(sb, srcs, 0, K, tid);

    const uint32_t lrow = (lane & 15);
    const uint32_t lcol16 = (lane >> 4) * 16;

    for (int c = 0; c < nch; c++) {
        if (c + 1 < nch) gm_load_stage(sb + ((c + 1) & 1) * GM_STAGE_B, srcs, (c + 1) << 5, K, tid);
        if (c + 1 < nch) { CP_WAIT(1); } else { CP_WAIT(0); }
        __syncthreads();

        const uint32_t st = sb + (c & 1) * GM_STAGE_B;
        #pragma unroll
        for (int ks = 0; ks < 2; ks++) {
            const uint32_t coff = lcol16 + ks * 32;
            uint32_t bh[2][4], bl[2][4];
            #pragma unroll
            for (int nt = 0; nt < 2; nt++) {
                const uint32_t baddr = st + 2 * GM_TILE_B
                    + (wn * 32 + nt * 16 + lrow) * (SAST * 2) + coff;
                ldsm_x4(bh[nt][0], bh[nt][1], bh[nt][2], bh[nt][3], baddr);
                ldsm_x4(bl[nt][0], bl[nt][1], bl[nt][2], bl[nt][3], baddr + GM_TILE_B);
            }
            #pragma unroll
            for (int mt = 0; mt < 4; mt++) {
                const uint32_t aaddr = st
                    + (wm * 64 + mt * 16 + lrow) * (SAST * 2) + coff;
                uint32_t ah[4], al[4];
                ldsm_x4(ah[0], ah[1], ah[2], ah[3], aaddr);
                ldsm_x4(al[0], al[1], al[2], al[3], aaddr + GM_TILE_B);
                #pragma unroll
                for (int nt = 0; nt < 2; nt++) {
                    #pragma unroll
                    for (int hh = 0; hh < 2; hh++) {
                        float* d = acc[mt][nt * 2 + hh];
                        uint32_t bfh0 = bh[nt][hh], bfh1 = bh[nt][hh + 2];
                        mma16816(d, ah, bfh0, bfh1);
                        mma16816(d, ah, bl[nt][hh], bl[nt][hh + 2]);
                        mma16816(d, al, bfh0, bfh1);
                    }
                }
            }
        }
        __syncthreads();
    }
}

// ---- plain epilogue (fp32 C) — out-projection ----
__global__ __launch_bounds__(256) void gemm_mma(
    const __nv_bfloat16* __restrict__ Ahi, const __nv_bfloat16* __restrict__ Alo,
    const __nv_bfloat16* __restrict__ Bhi, const __nv_bfloat16* __restrict__ Blo,
    float* __restrict__ C, int M, int N, int K)
{
    extern __shared__ __align__(128) char smem[];
    const uint32_t sb = smem_to_u32(smem);
    const int tid = threadIdx.x;
    const int lane = tid & 31;
    const int wid = tid >> 5;
    const int wm = wid & 1;
    const int wn = wid >> 1;
    const int bx = blockIdx.x, by = blockIdx.y;

    const __nv_bfloat16* srcs[4] = {
        Ahi + (size_t)(by * 128) * K, Alo + (size_t)(by * 128) * K,
        Bhi + (size_t)(bx * 128) * K, Blo + (size_t)(bx * 128) * K };

    float acc[4][4][4];
    #pragma unroll
    for (int a = 0; a < 4; a++)
        #pragma unroll
        for (int b = 0; b < 4; b++)
            #pragma unroll
            for (int c = 0; c < 4; c++) acc[a][b][c] = 0.f;

    gm_mainloop(sb, srcs, K, tid, lane, wm, wn, acc);

    #pragma unroll
    for (int mt = 0; mt < 4; mt++) {
        const int row0 = by * 128 + wm * 64 + mt * 16 + (lane >> 2);
        #pragma unroll
        for (int n8 = 0; n8 < 4; n8++) {
            const int col = bx * 128 + wn * 32 + n8 * 8 + (lane & 3) * 2;
            float2 o0 = make_float2(acc[mt][n8][0], acc[mt][n8][1]);
            float2 o1 = make_float2(acc[mt][n8][2], acc[mt][n8][3]);
            *(float2*)&C[(size_t)row0 * N + col]       = o0;
            *(float2*)&C[(size_t)(row0 + 8) * N + col] = o1;
        }
    }
}

// ---- RMS epilogue variant: fused RMSNorm + head-reshape + bf16 split ----
struct RmsDst {
    const float* w0;
    const float* w1;
    __nv_bfloat16 *h0, *l0;
    __nv_bfloat16 *h1, *l1;
    __nv_bfloat16 *h2, *l2;
    float qscale;
};

__global__ __launch_bounds__(256) void gemm_mma_rms(
    const __nv_bfloat16* __restrict__ Ahi, const __nv_bfloat16* __restrict__ Alo,
    const __nv_bfloat16* __restrict__ Bhi, const __nv_bfloat16* __restrict__ Blo,
    RmsDst P, int M, int N, int K)
{
    extern __shared__ __align__(128) char smem[];
    const uint32_t sb = smem_to_u32(smem);
    const int tid = threadIdx.x;
    const int lane = tid & 31;
    const int wid = tid >> 5;
    const int wm = wid & 1;
    const int wn = wid >> 1;
    const int bx = blockIdx.x, by = blockIdx.y;

    const __nv_bfloat16* srcs[4] = {
        Ahi + (size_t)(by * 128) * K, Alo + (size_t)(by * 128) * K,
        Bhi + (size_t)(bx * 128) * K, Blo + (size_t)(bx * 128) * K };

    float acc[4][4][4];
    #pragma unroll
    for (int a = 0; a < 4; a++)
        #pragma unroll
        for (int b = 0; b < 4; b++)
            #pragma unroll
            for (int c = 0; c < 4; c++) acc[a][b][c] = 0.f;

    gm_mainloop(sb, srcs, K, tid, lane, wm, wn, acc);

    // acc -> smem fp32 tile [128][132]
    float* sE = (float*)smem;
    #pragma unroll
    for (int mt = 0; mt < 4; mt++) {
        const int r0 = wm * 64 + mt * 16 + (lane >> 2);
        #pragma unroll
        for (int n8 = 0; n8 < 4; n8++) {
            const int c = wn * 32 + n8 * 8 + (lane & 3) * 2;
            *(float2*)&sE[r0 * 132 + c]       = make_float2(acc[mt][n8][0], acc[mt][n8][1]);
            *(float2*)&sE[(r0 + 8) * 132 + c] = make_float2(acc[mt][n8][2], acc[mt][n8][3]);
        }
    }
    __syncthreads();

    const int bq    = by >> 3;
    const int hloc  = lane >> 4;
    const int cg    = bx * 128 + hloc * 64;
    const int which = cg >> 10;
    const int hh    = (cg >> 6) & 15;
    const int d0    = (lane & 15) * 4;
    const bool donorm = (which < 2);
    const float* wptr = (which == 0) ? P.w0 : P.w1;
    float4 wv = make_float4(1.f, 1.f, 1.f, 1.f);
    if (donorm) wv = *(const float4*)&wptr[d0];
    __nv_bfloat16* dh = (which == 0) ? P.h0 : ((which == 1) ? P.h1 : P.h2);
    __nv_bfloat16* dl = (which == 0) ? P.l0 : ((which == 1) ? P.l1 : P.l2);
    const int w8 = wid * 16;

    #pragma unroll 4
    for (int i = 0; i < 16; i++) {
        const int r = w8 + i;
        float4 v = *(const float4*)&sE[r * 132 + lane * 4];
        float ss = v.x * v.x + v.y * v.y + v.z * v.z + v.w * v.w;
        ss += __shfl_xor_sync(0xffffffffu, ss, 1);
        ss += __shfl_xor_sync(0xffffffffu, ss, 2);
        ss += __shfl_xor_sync(0xffffffffu, ss, 4);
        ss += __shfl_xor_sync(0xffffffffu, ss, 8);
        const float rr = donorm ? rsqrtf(ss * (1.0f / 64.0f) + EPS_) * P.qscale : 1.f;
        const float f0 = v.x * rr * wv.x;
        const float f1 = v.y * rr * wv.y;
        const float f2 = v.z * rr * wv.z;
        const float f3 = v.w * rr * wv.w;
        const __nv_bfloat16 b0 = __float2bfloat16_rn(f0);
        const __nv_bfloat16 b1 = __float2bfloat16_rn(f1);
        const __nv_bfloat16 b2 = __float2bfloat16_rn(f2);
        const __nv_bfloat16 b3 = __float2bfloat16_rn(f3);
        const uint32_t H01 = pack_bf16(f0, f1);
        const uint32_t H23 = pack_bf16(f2, f3);
        const uint32_t L01 = pack_bf16(f0 - __bfloat162float(b0), f1 - __bfloat162float(b1));
        const uint32_t L23 = pack_bf16(f2 - __bfloat162float(b2), f3 - __bfloat162float(b3));
        const int t = (by & 7) * 128 + r;
        const size_t idx = ((((size_t)bq * 16 + hh) * 1024) + t) * 64 + d0;
        *(uint2*)&dh[idx] = make_uint2(H01, H23);
        *(uint2*)&dl[idx] = make_uint2(L01, L23);
    }
}

// ===========================================================================
// Dual flash attention — small CTA (2/SM), interleaved S1/S2 MMA streams,
// max-free softmax (S bounded ~|7| by construction; exp cannot overflow).
// ===========================================================================
#define FSTR_B    144
#define FQ_TILE   (64 * FSTR_B)             // 9216
#define FKV_TILE  (32 * FSTR_B)             // 4608
#define FKV_STAGE (6 * FKV_TILE)            // 27648
#define FLASH_SMEM (4 * FQ_TILE + 2 * FKV_STAGE)   // 92160

__device__ __forceinline__ void flash_load_kv6(
    uint32_t dst, const __nv_bfloat16* const* srcs, int kt, int tid)
{
    #pragma unroll
    for (int i = 0; i < 12; i++) {
        const int idx = tid + i * 128;
        const int t = idx >> 8;
        const int rem = idx & 255;
        const int row = rem >> 3, c = rem & 7;
        cp_async16(dst + t * FKV_TILE + row * FSTR_B + c * 16,
                   srcs[t] + ((size_t)(kt * 32 + row)) * HD_ + c * 8);
    }
}

// exp + row-sum (no max subtraction), accumulate into l
__device__ __forceinline__ void expsum4(float s[4][4], float l[2])
{
    float ps0 = 0.f, ps1 = 0.f;
    #pragma unroll
    for (int j = 0; j < 4; j++) {
        s[j][0] = __expf(s[j][0]);
        s[j][1] = __expf(s[j][1]);
        s[j][2] = __expf(s[j][2]);
        s[j][3] = __expf(s[j][3]);
        ps0 += s[j][0] + s[j][1];
        ps1 += s[j][2] + s[j][3];
    }
    ps0 += __shfl_xor_sync(0xffffffffu, ps0, 1);
    ps0 += __shfl_xor_sync(0xffffffffu, ps0, 2);
    ps1 += __shfl_xor_sync(0xffffffffu, ps1, 1);
    ps1 += __shfl_xor_sync(0xffffffffu, ps1, 2);
    l[0] += ps0;
    l[1] += ps1;
}

__device__ __forceinline__ void build_p4(const float s[4][4],
                                         uint32_t ph[2][4], uint32_t pl[2][4])
{
    #pragma unroll
    for (int kc = 0; kc < 2; kc++) {
        const int j0 = 2 * kc, j1 = 2 * kc + 1;
        ph[kc][0] = pack_bf16(s[j0][0], s[j0][1]);
        ph[kc][1] = pack_bf16(s[j0][2], s[j0][3]);
        ph[kc][2] = pack_bf16(s[j1][0], s[j1][1]);
        ph[kc][3] = pack_bf16(s[j1][2], s[j1][3]);
        float r00 = s[j0][0] - __bfloat162float(__float2bfloat16_rn(s[j0][0]));
        float r01 = s[j0][1] - __bfloat162float(__float2bfloat16_rn(s[j0][1]));
        float r02 = s[j0][2] - __bfloat162float(__float2bfloat16_rn(s[j0][2]));
        float r03 = s[j0][3] - __bfloat162float(__float2bfloat16_rn(s[j0][3]));
        float r10 = s[j1][0] - __bfloat162float(__float2bfloat16_rn(s[j1][0]));
        float r11 = s[j1][1] - __bfloat162float(__float2bfloat16_rn(s[j1][1]));
        float r12 = s[j1][2] - __bfloat162float(__float2bfloat16_rn(s[j1][2]));
        float r13 = s[j1][3] - __bfloat162float(__float2bfloat16_rn(s[j1][3]));
        pl[kc][0] = pack_bf16(r00, r01);
        pl[kc][1] = pack_bf16(r02, r03);
        pl[kc][2] = pack_bf16(r10, r11);
        pl[kc][3] = pack_bf16(r12, r13);
    }
}

__device__ __forceinline__ void pv_step4(float o[8][4], const uint32_t ph[2][4],
                                         const uint32_t pl[2][4], uint32_t st,
                                         uint32_t lrow16)
{
    #pragma unroll
    for (int kc = 0; kc < 2; kc++) {
        #pragma unroll
        for (int hg = 0; hg < 4; hg++) {
            const uint32_t addr = st + kc * 16 * FSTR_B + lrow16 + hg * 32;
            uint32_t vh0, vh1, vh2, vh3, vl0, vl1, vl2, vl3;
            ldsm_x4_t(vh0, vh1, vh2, vh3, addr + 4 * FKV_TILE);
            ldsm_x4_t(vl0, vl1, vl2, vl3, addr + 5 * FKV_TILE);
            mma16816(o[2 * hg],     ph[kc], vh0, vh1);
            mma16816(o[2 * hg],     pl[kc], vh0, vh1);
            mma16816(o[2 * hg],     ph[kc], vl0, vl1);
            mma16816(o[2 * hg + 1], ph[kc], vh2, vh3);
            mma16816(o[2 * hg + 1], pl[kc], vh2, vh3);
            mma16816(o[2 * hg + 1], ph[kc], vl2, vl3);
        }
    }
}

__global__ __launch_bounds__(128, 2) void flash_mma_kernel(
    const __nv_bfloat16* __restrict__ q1h, const __nv_bfloat16* __restrict__ q1l,
    const __nv_bfloat16* __restrict__ q2h, const __nv_bfloat16* __restrict__ q2l,
    const __nv_bfloat16* __restrict__ k1h, const __nv_bfloat16* __restrict__ k1l,
    const __nv_bfloat16* __restrict__ k2h, const __nv_bfloat16* __restrict__ k2l,
    const __nv_bfloat16* __restrict__ vhh, const __nv_bfloat16* __restrict__ vhl,
    const float* __restrict__ lmb, float* __restrict__ y)
{
    extern __shared__ __align__(128) char smem[];
    const uint32_t sb = smem_to_u32(smem);
    const uint32_t sQ = sb, sKV = sb + 4 * FQ_TILE;
    const int tid = threadIdx.x;
    const int lane = tid & 31;
    const int w = tid >> 5;
    const int qt = blockIdx.x, h = blockIdx.y, b = blockIdx.z;
    const int bh = b * H_ + h;
    const size_t off = (size_t)bh * TQ_ * HD_;

    const __nv_bfloat16* kvsrc[6] = {
        k1h + off, k1l + off, k2h + off, k2l + off, vhh + off, vhl + off };
    const __nv_bfloat16* qsrc[4] = {
        q1h + off, q1l + off, q2h + off, q2l + off };

    #pragma unroll
    for (int i = 0; i < 16; i++) {
        const int idx = tid + i * 128;
        const int ts = idx >> 9;
        const int rem = idx & 511;
        const int row = rem >> 3, c = rem & 7;
        cp_async16(sQ + ts * FQ_TILE + row * FSTR_B + c * 16,
                   qsrc[ts] + ((size_t)(qt * 64 + row)) * HD_ + c * 8);
    }
    flash_load_kv6(sKV, kvsrc, 0, tid);
    CP_COMMIT();
    flash_load_kv6(sKV + FKV_STAGE, kvsrc, 1, tid);
    CP_COMMIT();

    float o1[8][4], o2[8][4];
    float l1[2] = {0.f, 0.f}, l2[2] = {0.f, 0.f};
    #pragma unroll
    for (int j = 0; j < 8; j++)
        #pragma unroll
        for (int q = 0; q < 4; q++) { o1[j][q] = 0.f; o2[j][q] = 0.f; }

    CP_WAIT(1);
    __syncthreads();

    const uint32_t qrow = (w * 16 + (lane & 15)) * FSTR_B + (lane >> 4) * 16;
    const uint32_t lrow16 = (lane & 15) * FSTR_B + (lane >> 4) * 16;

    // Q1 fragments register-resident
    uint32_t q1hf[4][4], q1lf[4][4];
    #pragma unroll
    for (int kc = 0; kc < 4; kc++) {
        ldsm_x4(q1hf[kc][0], q1hf[kc][1], q1hf[kc][2], q1hf[kc][3],
                sQ + qrow + kc * 32);
        ldsm_x4(q1lf[kc][0], q1lf[kc][1], q1lf[kc][2], q1lf[kc][3],
                sQ + FQ_TILE + qrow + kc * 32);
    }

    for (int t = 0; t < 32; t++) {
        if (t > 0) {
            if (t + 1 < 32) { CP_WAIT(1); } else { CP_WAIT(0); }
            __syncthreads();
        }
        const uint32_t st = sKV + (t & 1) * FKV_STAGE;

        // ---- S1 MMA stream ----
        float s1[4][4];
        #pragma unroll
        for (int j = 0; j < 4; j++)
            #pragma unroll
            for (int q = 0; q < 4; q++) s1[j][q] = 0.f;

        #pragma unroll
        for (int kc = 0; kc < 4; kc++) {
            #pragma unroll
            for (int g = 0; g < 2; g++) {
                const uint32_t addr = st + g * 16 * FSTR_B + lrow16 + kc * 32;
                uint32_t h0, h1, h2, h3, l0r, l1r, l2r, l3r;
                ldsm_x4(h0, h1, h2, h3, addr);
                ldsm_x4(l0r, l1r, l2r, l3r, addr + FKV_TILE);
                mma16816(s1[2 * g],     q1hf[kc], h0, h2);
                mma16816(s1[2 * g],     q1hf[kc], l0r, l2r);
                mma16816(s1[2 * g],     q1lf[kc], h0, h2);
                mma16816(s1[2 * g + 1], q1hf[kc], h1, h3);
                mma16816(s1[2 * g + 1], q1hf[kc], l1r, l3r);
                mma16816(s1[2 * g + 1], q1lf[kc], h1, h3);
            }
        }

        // ---- S2 MMA stream (issues while s1 results drain) ----
        float s2[4][4];
        #pragma unroll
        for (int j = 0; j < 4; j++)
            #pragma unroll
            for (int q = 0; q < 4; q++) s2[j][q] = 0.f;

        #pragma unroll
        for (int kc = 0; kc < 4; kc++) {
            uint32_t qh[4], ql[4];
            ldsm_x4(qh[0], qh[1], qh[2], qh[3], sQ + 2 * FQ_TILE + qrow + kc * 32);
            ldsm_x4(ql[0], ql[1], ql[2], ql[3], sQ + 3 * FQ_TILE + qrow + kc * 32);
            #pragma unroll
            for (int g = 0; g < 2; g++) {
                const uint32_t addr = st + 2 * FKV_TILE + g * 16 * FSTR_B + lrow16 + kc * 32;
                uint32_t h0, h1, h2, h3, l0r, l1r, l2r, l3r;
                ldsm_x4(h0, h1, h2, h3, addr);
                ldsm_x4(l0r, l1r, l2r, l3r, addr + FKV_TILE);
                mma16816(s2[2 * g],     qh, h0, h2);
                mma16816(s2[2 * g],     qh, l0r, l2r);
                mma16816(s2[2 * g],     ql, h0, h2);
                mma16816(s2[2 * g + 1], qh, h1, h3);
                mma16816(s2[2 * g + 1], qh, l1r, l3r);
                mma16816(s2[2 * g + 1], ql, h1, h3);
            }
        }

        // ---- softmax1 (overlaps S2 MMA drain) + PV1 ----
        expsum4(s1, l1);
        {
            uint32_t ph[2][4], pl[2][4];
            build_p4(s1, ph, pl);
            pv_step4(o1, ph, pl, st, lrow16);
        }

        // ---- softmax2 (overlaps PV1 drain) + PV2 ----
        expsum4(s2, l2);
        {
            uint32_t ph[2][4], pl[2][4];
            build_p4(s2, ph, pl);
            pv_step4(o2, ph, pl, st, lrow16);
        }

        __syncthreads();
        if (t + 2 < 32) {
            flash_load_kv6(st, kvsrc, t + 2, tid);
            CP_COMMIT();
        }
    }

    // epilogue
    const float cmul = log1pf(__expf(lmb[h]));
    const int r0 = lane >> 2, cb = (lane & 3) * 2;
    const float il10 = 1.f / l1[0], il11 = 1.f / l1[1];
    const float il20 = cmul / l2[0], il21 = cmul / l2[1];
    const size_t ybase = off + (size_t)(qt * 64 + w * 16) * HD_;
    #pragma unroll
    for (int j = 0; j < 8; j++) {
        float2 v0 = make_float2(o1[j][0] * il10 - o2[j][0] * il20,
                                o1[j][1] * il10 - o2[j][1] * il20);
        float2 v1 = make_float2(o1[j][2] * il11 - o2[j][2] * il21,
                                o1[j][3] * il11 - o2[j][3] * il21);
        *(float2*)&y[ybase + (size_t)r0 * HD_ + j * 8 + cb]       = v0;
        *(float2*)&y[ybase + (size_t)(r0 + 8) * HD_ + j * 8 + cb] = v1;
    }
}

// ===========================================================================
// Merged GroupNorm: stats + apply + transpose + bf16 split, one block per (b,h)
// ===========================================================================
__global__ void gn_fused_kernel(const float* __restrict__ y,
                                const float* __restrict__ gw, const float* __restrict__ gb,
                                __nv_bfloat16* __restrict__ hi, __nv_bfloat16* __restrict__ lo)
{
    __shared__ float rs[256], rq[256];
    __shared__ float s_mu, s_rstd;
    const int bh = blockIdx.x, tid = threadIdx.x;
    const int b = bh >> 4, h = bh & 15;
    const float* p = y + (size_t)bh * TQ_ * HD_;

    float s = 0.f, q = 0.f;
    for (int i = tid * 4; i < TQ_ * HD_; i += 256 * 4) {
        float4 v = *(const float4*)(p + i);
        s += v.x + v.y + v.z + v.w;
        q += v.x * v.x + v.y * v.y + v.z * v.z + v.w * v.w;
    }
    rs[tid] = s; rq[tid] = q;
    __syncthreads();
    for (int o = 128; o; o >>= 1) {
        if (tid < o) { rs[tid] += rs[tid + o]; rq[tid] += rq[tid + o]; }
        __syncthreads();
    }
    if (tid == 0) {
        const float inv = 1.f / (float)(TQ_ * HD_);
        const float mu = rs[0] * inv;
        const float var = rq[0] * inv - mu * mu;
        s_mu = mu;
        s_rstd = rsqrtf(var + EPS_);
    }
    __syncthreads();
    const float mu = s_mu, rstd = s_rstd;

    for (int i = tid; i < TQ_ * HD_ / 4; i += 256) {
        const int t  = i >> 4;
        const int dd = (i & 15) * 4;
        float4 v = *(const float4*)(p + (size_t)t * HD_ + dd);
        float4 w = *(const float4*)&gw[h * 64 + dd];
        float4 bb = *(const float4*)&gb[h * 64 + dd];
        float f0 = (v.x - mu) * rstd * w.x + bb.x;
        float f1 = (v.y - mu) * rstd * w.y + bb.y;
        float f2 = (v.z - mu) * rstd * w.z + bb.z;
        float f3 = (v.w - mu) * rstd * w.w + bb.w;
        const __nv_bfloat16 b0 = __float2bfloat16_rn(f0);
        const __nv_bfloat16 b1 = __float2bfloat16_rn(f1);
        const __nv_bfloat16 b2 = __float2bfloat16_rn(f2);
        const __nv_bfloat16 b3 = __float2bfloat16_rn(f3);
        const size_t idx = ((size_t)(b * 1024 + t)) * 1024 + h * 64 + dd;
        *(uint2*)&hi[idx] = make_uint2(pack_bf16(f0, f1), pack_bf16(f2, f3));
        *(uint2*)&lo[idx] = make_uint2(
            pack_bf16(f0 - __bfloat162float(b0), f1 - __bfloat162float(b1)),
            pack_bf16(f2 - __bfloat162float(b2), f3 - __bfloat162float(b3)));
    }
}

// ===========================================================================
// Launch
// ===========================================================================
extern "C" void kernel_launch(void* const* d_in, const int* in_sizes, int n_in,
                              void* d_out, int out_size)
{
    const float* x_q  = (const float*)d_in[0];
    const float* x_kv = (const float*)d_in[1];
    const float* Wq   = (const float*)d_in[2];
    const float* Wkv  = (const float*)d_in[3];
    const float* Wc   = (const float*)d_in[4];
    const float* qn1  = (const float*)d_in[5];
    const float* kn1  = (const float*)d_in[6];
    const float* qn2  = (const float*)d_in[7];
    const float* kn2  = (const float*)d_in[8];
    const float* gn_w = (const float*)d_in[9];
    const float* gn_b = (const float*)d_in[10];
    const float* lmb  = (const float*)d_in[11];
    float* out = (float*)d_out;

    float *y;
    cudaGetSymbolAddress((void**)&y, g_y);

    __nv_bfloat16 *xq_hi, *xq_lo, *xkv_hi, *xkv_lo;
    __nv_bfloat16 *wqt_hi, *wqt_lo, *wkvt_hi, *wkvt_lo, *wct_hi, *wct_lo;
    __nv_bfloat16 *ybt_hi, *ybt_lo;
    __nv_bfloat16 *q1h, *q1l, *q2h, *q2l, *k1h, *k1l, *k2h, *k2l, *vhh, *vhl;
    cudaGetSymbolAddress((void**)&xq_hi,   g_xq_hi);
    cudaGetSymbolAddress((void**)&xq_lo,   g_xq_lo);
    cudaGetSymbolAddress((void**)&xkv_hi,  g_xkv_hi);
    cudaGetSymbolAddress((void**)&xkv_lo,  g_xkv_lo);
    cudaGetSymbolAddress((void**)&wqt_hi,  g_wqt_hi);
    cudaGetSymbolAddress((void**)&wqt_lo,  g_wqt_lo);
    cudaGetSymbolAddress((void**)&wkvt_hi, g_wkvt_hi);
    cudaGetSymbolAddress((void**)&wkvt_lo, g_wkvt_lo);
    cudaGetSymbolAddress((void**)&wct_hi,  g_wct_hi);
    cudaGetSymbolAddress((void**)&wct_lo,  g_wct_lo);
    cudaGetSymbolAddress((void**)&ybt_hi,  g_ybt_hi);
    cudaGetSymbolAddress((void**)&ybt_lo,  g_ybt_lo);
    cudaGetSymbolAddress((void**)&q1h, g_q1h);
    cudaGetSymbolAddress((void**)&q1l, g_q1l);
    cudaGetSymbolAddress((void**)&q2h, g_q2h);
    cudaGetSymbolAddress((void**)&q2l, g_q2l);
    cudaGetSymbolAddress((void**)&k1h, g_k1h);
    cudaGetSymbolAddress((void**)&k1l, g_k1l);
    cudaGetSymbolAddress((void**)&k2h, g_k2h);
    cudaGetSymbolAddress((void**)&k2l, g_k2l);
    cudaGetSymbolAddress((void**)&vhh, g_vhh);
    cudaGetSymbolAddress((void**)&vhl, g_vhl);

    const int M = B_ * TQ_;  // 4096

    cudaFuncSetAttribute(gemm_mma, cudaFuncAttributeMaxDynamicSharedMemorySize, GM_SMEM);
    cudaFuncSetAttribute(gemm_mma_rms, cudaFuncAttributeMaxDynamicSharedMemorySize, GM_SMEM);
    cudaFuncSetAttribute(flash_mma_kernel, cudaFuncAttributeMaxDynamicSharedMemorySize, FLASH_SMEM);

    // 0) split operands to bf16 hi/lo
    {
        const int n4 = M * D_ / 4;
        split2_kernel<<<dim3(n4 / 256, 2), 256>>>(x_q, xq_hi, xq_lo,
                                                  x_kv, xkv_hi, xkv_lo, n4);
        split_transpose_kernel<<<dim3(2 * D_ / 32, D_ / 32), dim3(32, 8)>>>(Wq,  wqt_hi,  wqt_lo,  D_, 2 * D_);
        split_transpose_kernel<<<dim3(3 * D_ / 32, D_ / 32), dim3(32, 8)>>>(Wkv, wkvt_hi, wkvt_lo, D_, 3 * D_);
        split_transpose_kernel<<<dim3(D_ / 32, D_ / 32),     dim3(32, 8)>>>(Wc,  wct_hi,  wct_lo,  D_, D_);
    }

    // 1) projections with fused RMSNorm + reshape + split (mma.sync bf16x3)
    {
        RmsDst Pq;
        Pq.w0 = qn1; Pq.w1 = qn2;
        Pq.h0 = q1h; Pq.l0 = q1l;
        Pq.h1 = q2h; Pq.l1 = q2l;
        Pq.h2 = nullptr; Pq.l2 = nullptr;
        Pq.qscale = 0.125f;
        gemm_mma_rms<<<dim3(2 * D_ / 128, M / 128), 256, GM_SMEM>>>(
            xq_hi, xq_lo, wqt_hi, wqt_lo, Pq, M, 2 * D_, D_);

        RmsDst Pkv;
        Pkv.w0 = kn1; Pkv.w1 = kn2;
        Pkv.h0 = k1h; Pkv.l0 = k1l;
        Pkv.h1 = k2h; Pkv.l1 = k2l;
        Pkv.h2 = vhh; Pkv.l2 = vhl;
        Pkv.qscale = 1.0f;
        gemm_mma_rms<<<dim3(3 * D_ / 128, M / 128), 256, GM_SMEM>>>(
            xkv_hi, xkv_lo, wkvt_hi, wkvt_lo, Pkv, M, 3 * D_, D_);
    }

    // 2) merged dual flash attention (small CTA, 2/SM, interleaved, max-free)
    flash_mma_kernel<<<dim3(TQ_ / 64, H_, B_), 128, FLASH_SMEM>>>(
        q1h, q1l, q2h, q2l, k1h, k1l, k2h, k2l, vhh, vhl, lmb, y);

    // 3) fused GroupNorm (stats + apply + transpose + split)
    gn_fused_kernel<<<B_ * H_, 256>>>(y, gn_w, gn_b, ybt_hi, ybt_lo);

    // 4) output projection (mma.sync bf16x3)
    gemm_mma<<<dim3(D_ / 128, M / 128), 256, GM_SMEM>>>(ybt_hi, ybt_lo, wct_hi, wct_lo, out, M, D_, D_);
}

// round 16
// speedup vs baseline: 1.1002x; 1.0024x over previous
#include <cuda_runtime.h>
#include <cuda_bf16.h>
#include <math.h>
#include <stdint.h>

// Problem constants
#define B_    4
#define TQ_   1024
#define TKV_  1024
#define D_    1024
#define H_    16
#define HD_   64
#define EPS_  1e-5f

// ===========================================================================
// PTX helpers (baseline features only — compute_103 virtual arch safe)
// ===========================================================================
__device__ __forceinline__ uint32_t smem_to_u32(const void* smem_ptr) {
    uint32_t addr;
    asm("{ .reg .u64 tmp; cvta.to.shared.u64 tmp, %1; cvt.u32.u64 %0, tmp; }"
        : "=r"(addr) : "l"(smem_ptr));
    return addr;
}

__device__ __forceinline__ void cp_async16(uint32_t dst, const void* src) {
    asm volatile("cp.async.cg.shared.global [%0], [%1], 16;" :: "r"(dst), "l"(src));
}
#define CP_COMMIT() asm volatile("cp.async.commit_group;" ::: "memory")
#define CP_WAIT(n)  asm volatile("cp.async.wait_group %0;" :: "n"(n) : "memory")

__device__ __forceinline__ void ldsm_x4(uint32_t& r0, uint32_t& r1, uint32_t& r2,
                                        uint32_t& r3, uint32_t addr) {
    asm volatile("ldmatrix.sync.aligned.m8n8.x4.shared.b16 {%0,%1,%2,%3}, [%4];"
        : "=r"(r0), "=r"(r1), "=r"(r2), "=r"(r3) : "r"(addr));
}

__device__ __forceinline__ void ldsm_x4_t(uint32_t& r0, uint32_t& r1, uint32_t& r2,
                                          uint32_t& r3, uint32_t addr) {
    asm volatile("ldmatrix.sync.aligned.m8n8.x4.trans.shared.b16 {%0,%1,%2,%3}, [%4];"
        : "=r"(r0), "=r"(r1), "=r"(r2), "=r"(r3) : "r"(addr));
}

// D += A * B  (m16n8k16, bf16 inputs, fp32 accum)
__device__ __forceinline__ void mma16816(float* d, const uint32_t* a,
                                         uint32_t b0, uint32_t b1) {
    asm volatile(
        "mma.sync.aligned.m16n8k16.row.col.f32.bf16.bf16.f32 "
        "{%0,%1,%2,%3}, {%4,%5,%6,%7}, {%8,%9}, {%0,%1,%2,%3};"
        : "+f"(d[0]), "+f"(d[1]), "+f"(d[2]), "+f"(d[3])
        : "r"(a[0]), "r"(a[1]), "r"(a[2]), "r"(a[3]), "r"(b0), "r"(b1));
}

__device__ __forceinline__ uint32_t pack_bf16(float a, float b) {
    __nv_bfloat162 t = __floats2bfloat162_rn(a, b);
    return *reinterpret_cast<uint32_t*>(&t);
}

// ===========================================================================
// Device scratch
// ===========================================================================
__device__ float g_y     [B_ * H_ * TQ_  * HD_];

__device__ __nv_bfloat16 g_xq_hi [B_ * TQ_ * D_];
__device__ __nv_bfloat16 g_xq_lo [B_ * TQ_ * D_];
__device__ __nv_bfloat16 g_xkv_hi[B_ * TKV_ * D_];
__device__ __nv_bfloat16 g_xkv_lo[B_ * TKV_ * D_];
__device__ __nv_bfloat16 g_wqt_hi [2 * D_ * D_];
__device__ __nv_bfloat16 g_wqt_lo [2 * D_ * D_];
__device__ __nv_bfloat16 g_wkvt_hi[3 * D_ * D_];
__device__ __nv_bfloat16 g_wkvt_lo[3 * D_ * D_];
__device__ __nv_bfloat16 g_wct_hi [D_ * D_];
__device__ __nv_bfloat16 g_wct_lo [D_ * D_];
__device__ __nv_bfloat16 g_ybt_hi [B_ * TQ_ * D_];
__device__ __nv_bfloat16 g_ybt_lo [B_ * TQ_ * D_];

// bf16 hi/lo attention operands, (B,H,T,HD)
__device__ __nv_bfloat16 g_q1h[B_ * H_ * TQ_ * HD_];
__device__ __nv_bfloat16 g_q1l[B_ * H_ * TQ_ * HD_];
__device__ __nv_bfloat16 g_q2h[B_ * H_ * TQ_ * HD_];
__device__ __nv_bfloat16 g_q2l[B_ * H_ * TQ_ * HD_];
__device__ __nv_bfloat16 g_k1h[B_ * H_ * TKV_ * HD_];
__device__ __nv_bfloat16 g_k1l[B_ * H_ * TKV_ * HD_];
__device__ __nv_bfloat16 g_k2h[B_ * H_ * TKV_ * HD_];
__device__ __nv_bfloat16 g_k2l[B_ * H_ * TKV_ * HD_];
__device__ __nv_bfloat16 g_vhh[B_ * H_ * TKV_ * HD_];
__device__ __nv_bfloat16 g_vhl[B_ * H_ * TKV_ * HD_];

// ===========================================================================
// Split fp32 -> bf16 hi/lo (both x tensors in one launch; grid.y selects)
// ===========================================================================
__global__ void split2_kernel(const float* __restrict__ xa,
                              __nv_bfloat16* __restrict__ hia, __nv_bfloat16* __restrict__ loa,
                              const float* __restrict__ xb,
                              __nv_bfloat16* __restrict__ hib, __nv_bfloat16* __restrict__ lob,
                              int n4)
{
    const int i = blockIdx.x * blockDim.x + threadIdx.x;
    if (i >= n4) return;
    const float* x = blockIdx.y ? xb : xa;
    __nv_bfloat16* hi = blockIdx.y ? hib : hia;
    __nv_bfloat16* lo = blockIdx.y ? lob : loa;
    float4 v = ((const float4*)x)[i];
    float f[4] = {v.x, v.y, v.z, v.w};
    __nv_bfloat16 h[4], l[4];
    #pragma unroll
    for (int j = 0; j < 4; j++) {
        h[j] = __float2bfloat16_rn(f[j]);
        l[j] = __float2bfloat16_rn(f[j] - __bfloat162float(h[j]));
    }
    ((__nv_bfloat162*)hi)[2*i + 0] = __nv_bfloat162(h[0], h[1]);
    ((__nv_bfloat162*)hi)[2*i + 1] = __nv_bfloat162(h[2], h[3]);
    ((__nv_bfloat162*)lo)[2*i + 0] = __nv_bfloat162(l[0], l[1]);
    ((__nv_bfloat162*)lo)[2*i + 1] = __nv_bfloat162(l[2], l[3]);
}

// ===========================================================================
// Transpose + split: W [K,N] fp32 -> Wt_hi/lo [N,K] bf16 (K-major)
// ===========================================================================
__global__ void split_transpose_kernel(const float* __restrict__ W,
                                       __nv_bfloat16* __restrict__ hi,
                                       __nv_bfloat16* __restrict__ lo, int K, int N)
{
    __shared__ float t[32][33];
    const int n0 = blockIdx.x * 32, k0 = blockIdx.y * 32;
    #pragma unroll
    for (int dy = 0; dy < 32; dy += 8)
        t[threadIdx.y + dy][threadIdx.x] =
            W[(size_t)(k0 + threadIdx.y + dy) * N + n0 + threadIdx.x];
    __syncthreads();
    #pragma unroll
    for (int dy = 0; dy < 32; dy += 8) {
        const int n = n0 + threadIdx.y + dy, k = k0 + threadIdx.x;
        const float v = t[threadIdx.x][threadIdx.y + dy];
        const __nv_bfloat16 h = __float2bfloat16_rn(v);
        hi[(size_t)n * K + k] = h;
        lo[(size_t)n * K + k] = __float2bfloat16_rn(v - __bfloat162float(h));
    }
}

// ===========================================================================
// mma.sync bf16x3 GEMM — now __launch_bounds__(256, 2) to force 2 CTAs/SM
// (regs capped at 128; smem 80KB x 2 = 160KB fits). Second CTA's HMMA stream
// covers this CTA's barrier/ldsm bubbles -> higher tensor-pipe activity.
// ===========================================================================
#define SAST       40
#define GM_TILE_B  (128 * SAST * 2)
#define GM_STAGE_B (4 * GM_TILE_B)
#define GM_SMEM    (2 * GM_STAGE_B)       // 81920

__device__ __forceinline__ void gm_load_stage(
    uint32_t stage_base, const __nv_bfloat16* const* srcs, int k0, int K, int tid)
{
    #pragma unroll
    for (int t = 0; t < 4; t++) {
        const __nv_bfloat16* s = srcs[t] + k0;
        const uint32_t tb = stage_base + t * GM_TILE_B;
        #pragma unroll
        for (int i = 0; i < 2; i++) {
            const int idx = tid + i * 256;
            const int row = idx >> 2, c16 = idx & 3;
            cp_async16(tb + row * (SAST * 2) + c16 * 16,
                       s + (size_t)row * K + c16 * 8);
        }
    }
    CP_COMMIT();
}

__device__ __forceinline__ void gm_mainloop(
    uint32_t sb, const __nv_bfloat16* const* srcs, int K,
    int tid, int lane, int wm, int wn, float acc[4][4][4])
{
    const int nch = K >> 5;
    gm_load_stage(sb, srcs, 0, K, tid);

    const uint32_t lrow = (lane & 15);
    const uint32_t lcol16 = (lane >> 4) * 16;

    for (int c = 0; c < nch; c++) {
        if (c + 1 < nch) gm_load_stage(sb + ((c + 1) & 1) * GM_STAGE_B, srcs, (c + 1) << 5, K, tid);
        if (c + 1 < nch) { CP_WAIT(1); } else { CP_WAIT(0); }
        __syncthreads();

        const uint32_t st = sb + (c & 1) * GM_STAGE_B;
        #pragma unroll
        for (int ks = 0; ks < 2; ks++) {
            const uint32_t coff = lcol16 + ks * 32;
            uint32_t bh[2][4], bl[2][4];
            #pragma unroll
            for (int nt = 0; nt < 2; nt++) {
                const uint32_t baddr = st + 2 * GM_TILE_B
                    + (wn * 32 + nt * 16 + lrow) * (SAST * 2) + coff;
                ldsm_x4(bh[nt][0], bh[nt][1], bh[nt][2], bh[nt][3], baddr);
                ldsm_x4(bl[nt][0], bl[nt][1], bl[nt][2], bl[nt][3], baddr + GM_TILE_B);
            }
            #pragma unroll
            for (int mt = 0; mt < 4; mt++) {
                const uint32_t aaddr = st
                    + (wm * 64 + mt * 16 + lrow) * (SAST * 2) + coff;
                uint32_t ah[4], al[4];
                ldsm_x4(ah[0], ah[1], ah[2], ah[3], aaddr);
                ldsm_x4(al[0], al[1], al[2], al[3], aaddr + GM_TILE_B);
                #pragma unroll
                for (int nt = 0; nt < 2; nt++) {
                    #pragma unroll
                    for (int hh = 0; hh < 2; hh++) {
                        float* d = acc[mt][nt * 2 + hh];
                        uint32_t bfh0 = bh[nt][hh], bfh1 = bh[nt][hh + 2];
                        mma16816(d, ah, bfh0, bfh1);
                        mma16816(d, ah, bl[nt][hh], bl[nt][hh + 2]);
                        mma16816(d, al, bfh0, bfh1);
                    }
                }
            }
        }
        __syncthreads();
    }
}

// ---- plain epilogue (fp32 C) — out-projection ----
__global__ __launch_bounds__(256, 2) void gemm_mma(
    const __nv_bfloat16* __restrict__ Ahi, const __nv_bfloat16* __restrict__ Alo,
    const __nv_bfloat16* __restrict__ Bhi, const __nv_bfloat16* __restrict__ Blo,
    float* __restrict__ C, int M, int N, int K)
{
    extern __shared__ __align__(128) char smem[];
    const uint32_t sb = smem_to_u32(smem);
    const int tid = threadIdx.x;
    const int lane = tid & 31;
    const int wid = tid >> 5;
    const int wm = wid & 1;
    const int wn = wid >> 1;
    const int bx = blockIdx.x, by = blockIdx.y;

    const __nv_bfloat16* srcs[4] = {
        Ahi + (size_t)(by * 128) * K, Alo + (size_t)(by * 128) * K,
        Bhi + (size_t)(bx * 128) * K, Blo + (size_t)(bx * 128) * K };

    float acc[4][4][4];
    #pragma unroll
    for (int a = 0; a < 4; a++)
        #pragma unroll
        for (int b = 0; b < 4; b++)
            #pragma unroll
            for (int c = 0; c < 4; c++) acc[a][b][c] = 0.f;

    gm_mainloop(sb, srcs, K, tid, lane, wm, wn, acc);

    #pragma unroll
    for (int mt = 0; mt < 4; mt++) {
        const int row0 = by * 128 + wm * 64 + mt * 16 + (lane >> 2);
        #pragma unroll
        for (int n8 = 0; n8 < 4; n8++) {
            const int col = bx * 128 + wn * 32 + n8 * 8 + (lane & 3) * 2;
            float2 o0 = make_float2(acc[mt][n8][0], acc[mt][n8][1]);
            float2 o1 = make_float2(acc[mt][n8][2], acc[mt][n8][3]);
            *(float2*)&C[(size_t)row0 * N + col]       = o0;
            *(float2*)&C[(size_t)(row0 + 8) * N + col] = o1;
        }
    }
}

// ---- RMS epilogue variant: fused RMSNorm + head-reshape + bf16 split ----
struct RmsDst {
    const float* w0;
    const float* w1;
    __nv_bfloat16 *h0, *l0;
    __nv_bfloat16 *h1, *l1;
    __nv_bfloat16 *h2, *l2;
    float qscale;
};

__global__ __launch_bounds__(256, 2) void gemm_mma_rms(
    const __nv_bfloat16* __restrict__ Ahi, const __nv_bfloat16* __restrict__ Alo,
    const __nv_bfloat16* __restrict__ Bhi, const __nv_bfloat16* __restrict__ Blo,
    RmsDst P, int M, int N, int K)
{
    extern __shared__ __align__(128) char smem[];
    const uint32_t sb = smem_to_u32(smem);
    const int tid = threadIdx.x;
    const int lane = tid & 31;
    const int wid = tid >> 5;
    const int wm = wid & 1;
    const int wn = wid >> 1;
    const int bx = blockIdx.x, by = blockIdx.y;

    const __nv_bfloat16* srcs[4] = {
        Ahi + (size_t)(by * 128) * K, Alo + (size_t)(by * 128) * K,
        Bhi + (size_t)(bx * 128) * K, Blo + (size_t)(bx * 128) * K };

    float acc[4][4][4];
    #pragma unroll
    for (int a = 0; a < 4; a++)
        #pragma unroll
        for (int b = 0; b < 4; b++)
            #pragma unroll
            for (int c = 0; c < 4; c++) acc[a][b][c] = 0.f;

    gm_mainloop(sb, srcs, K, tid, lane, wm, wn, acc);

    // acc -> smem fp32 tile [128][132]
    float* sE = (float*)smem;
    #pragma unroll
    for (int mt = 0; mt < 4; mt++) {
        const int r0 = wm * 64 + mt * 16 + (lane >> 2);
        #pragma unroll
        for (int n8 = 0; n8 < 4; n8++) {
            const int c = wn * 32 + n8 * 8 + (lane & 3) * 2;
            *(float2*)&sE[r0 * 132 + c]       = make_float2(acc[mt][n8][0], acc[mt][n8][1]);
            *(float2*)&sE[(r0 + 8) * 132 + c] = make_float2(acc[mt][n8][2], acc[mt][n8][3]);
        }
    }
    __syncthreads();

    const int bq    = by >> 3;
    const int hloc  = lane >> 4;
    const int cg    = bx * 128 + hloc * 64;
    const int which = cg >> 10;
    const int hh    = (cg >> 6) & 15;
    const int d0    = (lane & 15) * 4;
    const bool donorm = (which < 2);
    const float* wptr = (which == 0) ? P.w0 : P.w1;
    float4 wv = make_float4(1.f, 1.f, 1.f, 1.f);
    if (donorm) wv = *(const float4*)&wptr[d0];
    __nv_bfloat16* dh = (which == 0) ? P.h0 : ((which == 1) ? P.h1 : P.h2);
    __nv_bfloat16* dl = (which == 0) ? P.l0 : ((which == 1) ? P.l1 : P.l2);
    const int w8 = wid * 16;

    #pragma unroll 4
    for (int i = 0; i < 16; i++) {
        const int r = w8 + i;
        float4 v = *(const float4*)&sE[r * 132 + lane * 4];
        float ss = v.x * v.x + v.y * v.y + v.z * v.z + v.w * v.w;
        ss += __shfl_xor_sync(0xffffffffu, ss, 1);
        ss += __shfl_xor_sync(0xffffffffu, ss, 2);
        ss += __shfl_xor_sync(0xffffffffu, ss, 4);
        ss += __shfl_xor_sync(0xffffffffu, ss, 8);
        const float rr = donorm ? rsqrtf(ss * (1.0f / 64.0f) + EPS_) * P.qscale : 1.f;
        const float f0 = v.x * rr * wv.x;
        const float f1 = v.y * rr * wv.y;
        const float f2 = v.z * rr * wv.z;
        const float f3 = v.w * rr * wv.w;
        const __nv_bfloat16 b0 = __float2bfloat16_rn(f0);
        const __nv_bfloat16 b1 = __float2bfloat16_rn(f1);
        const __nv_bfloat16 b2 = __float2bfloat16_rn(f2);
        const __nv_bfloat16 b3 = __float2bfloat16_rn(f3);
        const uint32_t H01 = pack_bf16(f0, f1);
        const uint32_t H23 = pack_bf16(f2, f3);
        const uint32_t L01 = pack_bf16(f0 - __bfloat162float(b0), f1 - __bfloat162float(b1));
        const uint32_t L23 = pack_bf16(f2 - __bfloat162float(b2), f3 - __bfloat162float(b3));
        const int t = (by & 7) * 128 + r;
        const size_t idx = ((((size_t)bq * 16 + hh) * 1024) + t) * 64 + d0;
        *(uint2*)&dh[idx] = make_uint2(H01, H23);
        *(uint2*)&dl[idx] = make_uint2(L01, L23);
    }
}

// ===========================================================================
// Dual flash attention — small CTA (2/SM), interleaved S1/S2 MMA streams,
// max-free softmax (S bounded ~|7| by construction; exp cannot overflow).
// ===========================================================================
#define FSTR_B    144
#define FQ_TILE   (64 * FSTR_B)             // 9216
#define FKV_TILE  (32 * FSTR_B)             // 4608
#define FKV_STAGE (6 * FKV_TILE)            // 27648
#define FLASH_SMEM (4 * FQ_TILE + 2 * FKV_STAGE)   // 92160

__device__ __forceinline__ void flash_load_kv6(
    uint32_t dst, const __nv_bfloat16* const* srcs, int kt, int tid)
{
    #pragma unroll
    for (int i = 0; i < 12; i++) {
        const int idx = tid + i * 128;
        const int t = idx >> 8;
        const int rem = idx & 255;
        const int row = rem >> 3, c = rem & 7;
        cp_async16(dst + t * FKV_TILE + row * FSTR_B + c * 16,
                   srcs[t] + ((size_t)(kt * 32 + row)) * HD_ + c * 8);
    }
}

// exp + row-sum (no max subtraction), accumulate into l
__device__ __forceinline__ void expsum4(float s[4][4], float l[2])
{
    float ps0 = 0.f, ps1 = 0.f;
    #pragma unroll
    for (int j = 0; j < 4; j++) {
        s[j][0] = __expf(s[j][0]);
        s[j][1] = __expf(s[j][1]);
        s[j][2] = __expf(s[j][2]);
        s[j][3] = __expf(s[j][3]);
        ps0 += s[j][0] + s[j][1];
        ps1 += s[j][2] + s[j][3];
    }
    ps0 += __shfl_xor_sync(0xffffffffu, ps0, 1);
    ps0 += __shfl_xor_sync(0xffffffffu, ps0, 2);
    ps1 += __shfl_xor_sync(0xffffffffu, ps1, 1);
    ps1 += __shfl_xor_sync(0xffffffffu, ps1, 2);
    l[0] += ps0;
    l[1] += ps1;
}

__device__ __forceinline__ void build_p4(const float s[4][4],
                                         uint32_t ph[2][4], uint32_t pl[2][4])
{
    #pragma unroll
    for (int kc = 0; kc < 2; kc++) {
        const int j0 = 2 * kc, j1 = 2 * kc + 1;
        ph[kc][0] = pack_bf16(s[j0][0], s[j0][1]);
        ph[kc][1] = pack_bf16(s[j0][2], s[j0][3]);
        ph[kc][2] = pack_bf16(s[j1][0], s[j1][1]);
        ph[kc][3] = pack_bf16(s[j1][2], s[j1][3]);
        float r00 = s[j0][0] - __bfloat162float(__float2bfloat16_rn(s[j0][0]));
        float r01 = s[j0][1] - __bfloat162float(__float2bfloat16_rn(s[j0][1]));
        float r02 = s[j0][2] - __bfloat162float(__float2bfloat16_rn(s[j0][2]));
        float r03 = s[j0][3] - __bfloat162float(__float2bfloat16_rn(s[j0][3]));
        float r10 = s[j1][0] - __bfloat162float(__float2bfloat16_rn(s[j1][0]));
        float r11 = s[j1][1] - __bfloat162float(__float2bfloat16_rn(s[j1][1]));
        float r12 = s[j1][2] - __bfloat162float(__float2bfloat16_rn(s[j1][2]));
        float r13 = s[j1][3] - __bfloat162float(__float2bfloat16_rn(s[j1][3]));
        pl[kc][0] = pack_bf16(r00, r01);
        pl[kc][1] = pack_bf16(r02, r03);
        pl[kc][2] = pack_bf16(r10, r11);
        pl[kc][3] = pack_bf16(r12, r13);
    }
}

__device__ __forceinline__ void pv_step4(float o[8][4], const uint32_t ph[2][4],
                                         const uint32_t pl[2][4], uint32_t st,
                                         uint32_t lrow16)
{
    #pragma unroll
    for (int kc = 0; kc < 2; kc++) {
        #pragma unroll
        for (int hg = 0; hg < 4; hg++) {
            const uint32_t addr = st + kc * 16 * FSTR_B + lrow16 + hg * 32;
            uint32_t vh0, vh1, vh2, vh3, vl0, vl1, vl2, vl3;
            ldsm_x4_t(vh0, vh1, vh2, vh3, addr + 4 * FKV_TILE);
            ldsm_x4_t(vl0, vl1, vl2, vl3, addr + 5 * FKV_TILE);
            mma16816(o[2 * hg],     ph[kc], vh0, vh1);
            mma16816(o[2 * hg],     pl[kc], vh0, vh1);
            mma16816(o[2 * hg],     ph[kc], vl0, vl1);
            mma16816(o[2 * hg + 1], ph[kc], vh2, vh3);
            mma16816(o[2 * hg + 1], pl[kc], vh2, vh3);
            mma16816(o[2 * hg + 1], ph[kc], vl2, vl3);
        }
    }
}

__global__ __launch_bounds__(128, 2) void flash_mma_kernel(
    const __nv_bfloat16* __restrict__ q1h, const __nv_bfloat16* __restrict__ q1l,
    const __nv_bfloat16* __restrict__ q2h, const __nv_bfloat16* __restrict__ q2l,
    const __nv_bfloat16* __restrict__ k1h, const __nv_bfloat16* __restrict__ k1l,
    const __nv_bfloat16* __restrict__ k2h, const __nv_bfloat16* __restrict__ k2l,
    const __nv_bfloat16* __restrict__ vhh, const __nv_bfloat16* __restrict__ vhl,
    const float* __restrict__ lmb, float* __restrict__ y)
{
    extern __shared__ __align__(128) char smem[];
    const uint32_t sb = smem_to_u32(smem);
    const uint32_t sQ = sb, sKV = sb + 4 * FQ_TILE;
    const int tid = threadIdx.x;
    const int lane = tid & 31;
    const int w = tid >> 5;
    const int qt = blockIdx.x, h = blockIdx.y, b = blockIdx.z;
    const int bh = b * H_ + h;
    const size_t off = (size_t)bh * TQ_ * HD_;

    const __nv_bfloat16* kvsrc[6] = {
        k1h + off, k1l + off, k2h + off, k2l + off, vhh + off, vhl + off };
    const __nv_bfloat16* qsrc[4] = {
        q1h + off, q1l + off, q2h + off, q2l + off };

    #pragma unroll
    for (int i = 0; i < 16; i++) {
        const int idx = tid + i * 128;
        const int ts = idx >> 9;
        const int rem = idx & 511;
        const int row = rem >> 3, c = rem & 7;
        cp_async16(sQ + ts * FQ_TILE + row * FSTR_B + c * 16,
                   qsrc[ts] + ((size_t)(qt * 64 + row)) * HD_ + c * 8);
    }
    flash_load_kv6(sKV, kvsrc, 0, tid);
    CP_COMMIT();
    flash_load_kv6(sKV + FKV_STAGE, kvsrc, 1, tid);
    CP_COMMIT();

    float o1[8][4], o2[8][4];
    float l1[2] = {0.f, 0.f}, l2[2] = {0.f, 0.f};
    #pragma unroll
    for (int j = 0; j < 8; j++)
        #pragma unroll
        for (int q = 0; q < 4; q++) { o1[j][q] = 0.f; o2[j][q] = 0.f; }

    CP_WAIT(1);
    __syncthreads();

    const uint32_t qrow = (w * 16 + (lane & 15)) * FSTR_B + (lane >> 4) * 16;
    const uint32_t lrow16 = (lane & 15) * FSTR_B + (lane >> 4) * 16;

    // Q1 fragments register-resident
    uint32_t q1hf[4][4], q1lf[4][4];
    #pragma unroll
    for (int kc = 0; kc < 4; kc++) {
        ldsm_x4(q1hf[kc][0], q1hf[kc][1], q1hf[kc][2], q1hf[kc][3],
                sQ + qrow + kc * 32);
        ldsm_x4(q1lf[kc][0], q1lf[kc][1], q1lf[kc][2], q1lf[kc][3],
                sQ + FQ_TILE + qrow + kc * 32);
    }

    for (int t = 0; t < 32; t++) {
        if (t > 0) {
            if (t + 1 < 32) { CP_WAIT(1); } else { CP_WAIT(0); }
            __syncthreads();
        }
        const uint32_t st = sKV + (t & 1) * FKV_STAGE;

        // ---- S1 MMA stream ----
        float s1[4][4];
        #pragma unroll
        for (int j = 0; j < 4; j++)
            #pragma unroll
            for (int q = 0; q < 4; q++) s1[j][q] = 0.f;

        #pragma unroll
        for (int kc = 0; kc < 4; kc++) {
            #pragma unroll
            for (int g = 0; g < 2; g++) {
                const uint32_t addr = st + g * 16 * FSTR_B + lrow16 + kc * 32;
                uint32_t h0, h1, h2, h3, l0r, l1r, l2r, l3r;
                ldsm_x4(h0, h1, h2, h3, addr);
                ldsm_x4(l0r, l1r, l2r, l3r, addr + FKV_TILE);
                mma16816(s1[2 * g],     q1hf[kc], h0, h2);
                mma16816(s1[2 * g],     q1hf[kc], l0r, l2r);
                mma16816(s1[2 * g],     q1lf[kc], h0, h2);
                mma16816(s1[2 * g + 1], q1hf[kc], h1, h3);
                mma16816(s1[2 * g + 1], q1hf[kc], l1r, l3r);
                mma16816(s1[2 * g + 1], q1lf[kc], h1, h3);
            }
        }

        // ---- S2 MMA stream (issues while s1 results drain) ----
        float s2[4][4];
        #pragma unroll
        for (int j = 0; j < 4; j++)
            #pragma unroll
            for (int q = 0; q < 4; q++) s2[j][q] = 0.f;

        #pragma unroll
        for (int kc = 0; kc < 4; kc++) {
            uint32_t qh[4], ql[4];
            ldsm_x4(qh[0], qh[1], qh[2], qh[3], sQ + 2 * FQ_TILE + qrow + kc * 32);
            ldsm_x4(ql[0], ql[1], ql[2], ql[3], sQ + 3 * FQ_TILE + qrow + kc * 32);
            #pragma unroll
            for (int g = 0; g < 2; g++) {
                const uint32_t addr = st + 2 * FKV_TILE + g * 16 * FSTR_B + lrow16 + kc * 32;
                uint32_t h0, h1, h2, h3, l0r, l1r, l2r, l3r;
                ldsm_x4(h0, h1, h2, h3, addr);
                ldsm_x4(l0r, l1r, l2r, l3r, addr + FKV_TILE);
                mma16816(s2[2 * g],     qh, h0, h2);
                mma16816(s2[2 * g],     qh, l0r, l2r);
                mma16816(s2[2 * g],     ql, h0, h2);
                mma16816(s2[2 * g + 1], qh, h1, h3);
                mma16816(s2[2 * g + 1], qh, l1r, l3r);
                mma16816(s2[2 * g + 1], ql, h1, h3);
            }
        }

        // ---- softmax1 (overlaps S2 MMA drain) + PV1 ----
        expsum4(s1, l1);
        {
            uint32_t ph[2][4], pl[2][4];
            build_p4(s1, ph, pl);
            pv_step4(o1, ph, pl, st, lrow16);
        }

        // ---- softmax2 (overlaps PV1 drain) + PV2 ----
        expsum4(s2, l2);
        {
            uint32_t ph[2][4], pl[2][4];
            build_p4(s2, ph, pl);
            pv_step4(o2, ph, pl, st, lrow16);
        }

        __syncthreads();
        if (t + 2 < 32) {
            flash_load_kv6(st, kvsrc, t + 2, tid);
            CP_COMMIT();
        }
    }

    // epilogue
    const float cmul = log1pf(__expf(lmb[h]));
    const int r0 = lane >> 2, cb = (lane & 3) * 2;
    const float il10 = 1.f / l1[0], il11 = 1.f / l1[1];
    const float il20 = cmul / l2[0], il21 = cmul / l2[1];
    const size_t ybase = off + (size_t)(qt * 64 + w * 16) * HD_;
    #pragma unroll
    for (int j = 0; j < 8; j++) {
        float2 v0 = make_float2(o1[j][0] * il10 - o2[j][0] * il20,
                                o1[j][1] * il10 - o2[j][1] * il20);
        float2 v1 = make_float2(o1[j][2] * il11 - o2[j][2] * il21,
                                o1[j][3] * il11 - o2[j][3] * il21);
        *(float2*)&y[ybase + (size_t)r0 * HD_ + j * 8 + cb]       = v0;
        *(float2*)&y[ybase + (size_t)(r0 + 8) * HD_ + j * 8 + cb] = v1;
    }
}

// ===========================================================================
// Merged GroupNorm: stats + apply + transpose + bf16 split, one block per (b,h)
// ===========================================================================
__global__ void gn_fused_kernel(const float* __restrict__ y,
                                const float* __restrict__ gw, const float* __restrict__ gb,
                                __nv_bfloat16* __restrict__ hi, __nv_bfloat16* __restrict__ lo)
{
    __shared__ float rs[256], rq[256];
    __shared__ float s_mu, s_rstd;
    const int bh = blockIdx.x, tid = threadIdx.x;
    const int b = bh >> 4, h = bh & 15;
    const float* p = y + (size_t)bh * TQ_ * HD_;

    float s = 0.f, q = 0.f;
    for (int i = tid * 4; i < TQ_ * HD_; i += 256 * 4) {
        float4 v = *(const float4*)(p + i);
        s += v.x + v.y + v.z + v.w;
        q += v.x * v.x + v.y * v.y + v.z * v.z + v.w * v.w;
    }
    rs[tid] = s; rq[tid] = q;
    __syncthreads();
    for (int o = 128; o; o >>= 1) {
        if (tid < o) { rs[tid] += rs[tid + o]; rq[tid] += rq[tid + o]; }
        __syncthreads();
    }
    if (tid == 0) {
        const float inv = 1.f / (float)(TQ_ * HD_);
        const float mu = rs[0] * inv;
        const float var = rq[0] * inv - mu * mu;
        s_mu = mu;
        s_rstd = rsqrtf(var + EPS_);
    }
    __syncthreads();
    const float mu = s_mu, rstd = s_rstd;

    for (int i = tid; i < TQ_ * HD_ / 4; i += 256) {
        const int t  = i >> 4;
        const int dd = (i & 15) * 4;
        float4 v = *(const float4*)(p + (size_t)t * HD_ + dd);
        float4 w = *(const float4*)&gw[h * 64 + dd];
        float4 bb = *(const float4*)&gb[h * 64 + dd];
        float f0 = (v.x - mu) * rstd * w.x + bb.x;
        float f1 = (v.y - mu) * rstd * w.y + bb.y;
        float f2 = (v.z - mu) * rstd * w.z + bb.z;
        float f3 = (v.w - mu) * rstd * w.w + bb.w;
        const __nv_bfloat16 b0 = __float2bfloat16_rn(f0);
        const __nv_bfloat16 b1 = __float2bfloat16_rn(f1);
        const __nv_bfloat16 b2 = __float2bfloat16_rn(f2);
        const __nv_bfloat16 b3 = __float2bfloat16_rn(f3);
        const size_t idx = ((size_t)(b * 1024 + t)) * 1024 + h * 64 + dd;
        *(uint2*)&hi[idx] = make_uint2(pack_bf16(f0, f1), pack_bf16(f2, f3));
        *(uint2*)&lo[idx] = make_uint2(
            pack_bf16(f0 - __bfloat162float(b0), f1 - __bfloat162float(b1)),
            pack_bf16(f2 - __bfloat162float(b2), f3 - __bfloat162float(b3)));
    }
}

// ===========================================================================
// Launch
// ===========================================================================
extern "C" void kernel_launch(void* const* d_in, const int* in_sizes, int n_in,
                              void* d_out, int out_size)
{
    const float* x_q  = (const float*)d_in[0];
    const float* x_kv = (const float*)d_in[1];
    const float* Wq   = (const float*)d_in[2];
    const float* Wkv  = (const float*)d_in[3];
    const float* Wc   = (const float*)d_in[4];
    const float* qn1  = (const float*)d_in[5];
    const float* kn1  = (const float*)d_in[6];
    const float* qn2  = (const float*)d_in[7];
    const float* kn2  = (const float*)d_in[8];
    const float* gn_w = (const float*)d_in[9];
    const float* gn_b = (const float*)d_in[10];
    const float* lmb  = (const float*)d_in[11];
    float* out = (float*)d_out;

    float *y;
    cudaGetSymbolAddress((void**)&y, g_y);

    __nv_bfloat16 *xq_hi, *xq_lo, *xkv_hi, *xkv_lo;
    __nv_bfloat16 *wqt_hi, *wqt_lo, *wkvt_hi, *wkvt_lo, *wct_hi, *wct_lo;
    __nv_bfloat16 *ybt_hi, *ybt_lo;
    __nv_bfloat16 *q1h, *q1l, *q2h, *q2l, *k1h, *k1l, *k2h, *k2l, *vhh, *vhl;
    cudaGetSymbolAddress((void**)&xq_hi,   g_xq_hi);
    cudaGetSymbolAddress((void**)&xq_lo,   g_xq_lo);
    cudaGetSymbolAddress((void**)&xkv_hi,  g_xkv_hi);
    cudaGetSymbolAddress((void**)&xkv_lo,  g_xkv_lo);
    cudaGetSymbolAddress((void**)&wqt_hi,  g_wqt_hi);
    cudaGetSymbolAddress((void**)&wqt_lo,  g_wqt_lo);
    cudaGetSymbolAddress((void**)&wkvt_hi, g_wkvt_hi);
    cudaGetSymbolAddress((void**)&wkvt_lo, g_wkvt_lo);
    cudaGetSymbolAddress((void**)&wct_hi,  g_wct_hi);
    cudaGetSymbolAddress((void**)&wct_lo,  g_wct_lo);
    cudaGetSymbolAddress((void**)&ybt_hi,  g_ybt_hi);
    cudaGetSymbolAddress((void**)&ybt_lo,  g_ybt_lo);
    cudaGetSymbolAddress((void**)&q1h, g_q1h);
    cudaGetSymbolAddress((void**)&q1l, g_q1l);
    cudaGetSymbolAddress((void**)&q2h, g_q2h);
    cudaGetSymbolAddress((void**)&q2l, g_q2l);
    cudaGetSymbolAddress((void**)&k1h, g_k1h);
    cudaGetSymbolAddress((void**)&k1l, g_k1l);
    cudaGetSymbolAddress((void**)&k2h, g_k2h);
    cudaGetSymbolAddress((void**)&k2l, g_k2l);
    cudaGetSymbolAddress((void**)&vhh, g_vhh);
    cudaGetSymbolAddress((void**)&vhl, g_vhl);

    const int M = B_ * TQ_;  // 4096

    cudaFuncSetAttribute(gemm_mma, cudaFuncAttributeMaxDynamicSharedMemorySize, GM_SMEM);
    cudaFuncSetAttribute(gemm_mma_rms, cudaFuncAttributeMaxDynamicSharedMemorySize, GM_SMEM);
    cudaFuncSetAttribute(flash_mma_kernel, cudaFuncAttributeMaxDynamicSharedMemorySize, FLASH_SMEM);

    // 0) split operands to bf16 hi/lo
    {
        const int n4 = M * D_ / 4;
        split2_kernel<<<dim3(n4 / 256, 2), 256>>>(x_q, xq_hi, xq_lo,
                                                  x_kv, xkv_hi, xkv_lo, n4);
        split_transpose_kernel<<<dim3(2 * D_ / 32, D_ / 32), dim3(32, 8)>>>(Wq,  wqt_hi,  wqt_lo,  D_, 2 * D_);
        split_transpose_kernel<<<dim3(3 * D_ / 32, D_ / 32), dim3(32, 8)>>>(Wkv, wkvt_hi, wkvt_lo, D_, 3 * D_);
        split_transpose_kernel<<<dim3(D_ / 32, D_ / 32),     dim3(32, 8)>>>(Wc,  wct_hi,  wct_lo,  D_, D_);
    }

    // 1) projections with fused RMSNorm + reshape + split (mma.sync bf16x3)
    {
        RmsDst Pq;
        Pq.w0 = qn1; Pq.w1 = qn2;
        Pq.h0 = q1h; Pq.l0 = q1l;
        Pq.h1 = q2h; Pq.l1 = q2l;
        Pq.h2 = nullptr; Pq.l2 = nullptr;
        Pq.qscale = 0.125f;
        gemm_mma_rms<<<dim3(2 * D_ / 128, M / 128), 256, GM_SMEM>>>(
            xq_hi, xq_lo, wqt_hi, wqt_lo, Pq, M, 2 * D_, D_);

        RmsDst Pkv;
        Pkv.w0 = kn1; Pkv.w1 = kn2;
        Pkv.h0 = k1h; Pkv.l0 = k1l;
        Pkv.h1 = k2h; Pkv.l1 = k2l;
        Pkv.h2 = vhh; Pkv.l2 = vhl;
        Pkv.qscale = 1.0f;
        gemm_mma_rms<<<dim3(3 * D_ / 128, M / 128), 256, GM_SMEM>>>(
            xkv_hi, xkv_lo, wkvt_hi, wkvt_lo, Pkv, M, 3 * D_, D_);
    }

    // 2) merged dual flash attention (small CTA, 2/SM, interleaved, max-free)
    flash_mma_kernel<<<dim3(TQ_ / 64, H_, B_), 128, FLASH_SMEM>>>(
        q1h, q1l, q2h, q2l, k1h, k1l, k2h, k2l, vhh, vhl, lmb, y);

    // 3) fused GroupNorm (stats + apply + transpose + split)
    gn_fused_kernel<<<B_ * H_, 256>>>(y, gn_w, gn_b, ybt_hi, ybt_lo);

    // 4) output projection (mma.sync bf16x3)
    gemm_mma<<<dim3(D_ / 128, M / 128), 256, GM_SMEM>>>(ybt_hi, ybt_lo, wct_hi, wct_lo, out, M, D_, D_);
}